// round 1
// baseline (speedup 1.0000x reference)
#include <cuda_runtime.h>
#include <cstdint>
#include <math.h>

// ---------------- problem constants ----------------
#define T_TOK 8192      // B*S tokens
#define HDIM  1024
#define FDIM  4096
#define NEXP  8
#define TOPK  2

// ---------------- GEMM tiling ----------------
#define BM 128
#define BN 128
#define BK 16
#define MAXTILES 136                 // ceil(16384/128) + NEXP padding tiles
#define ROWCAP   (MAXTILES * BM)     // 17408 padded rows

// ---------------- scratch (static device globals; no allocs) ----------------
__device__ float g_scr1[(size_t)ROWCAP * FDIM];   // gelu(x@w1+b1), tf32-rounded
__device__ float g_scr2[(size_t)ROWCAP * HDIM];   // wt*(h@w2+b2)
__device__ int   g_pair_tok[ROWCAP];
__device__ float g_pair_wt[ROWCAP];
__device__ int   g_row_of[T_TOK * TOPK];
__device__ int   g_tok_eid[T_TOK * TOPK];
__device__ float g_tok_w[T_TOK * TOPK];
__device__ int   g_counts[NEXP];
__device__ int   g_cursor[NEXP];
__device__ int   g_tile_e[MAXTILES];
__device__ int   g_num_tiles;

// ---------------- helpers ----------------
__device__ __forceinline__ float to_tf32(float x) {
    uint32_t u;
    asm("cvt.rna.tf32.f32 %0, %1;" : "=r"(u) : "f"(x));
    return __uint_as_float(u);
}

__device__ __forceinline__ float4 tf32x4(float4 v) {
    float4 r;
    r.x = to_tf32(v.x); r.y = to_tf32(v.y);
    r.z = to_tf32(v.z); r.w = to_tf32(v.w);
    return r;
}

__device__ __forceinline__ float gelu_tanh(float v) {
    // jax.nn.gelu default (approximate=True): 0.5*v*(1+tanh(sqrt(2/pi)*(v+0.044715*v^3)))
    float u = v * (0.7978845608028654f + 0.03567740813636141f * v * v);
    return 0.5f * v * (1.0f + tanhf(u));
}

__device__ __forceinline__ void mma_tf32(float* d, const uint32_t* a, const uint32_t* b) {
    asm volatile(
        "mma.sync.aligned.m16n8k8.row.col.f32.tf32.tf32.f32 "
        "{%0,%1,%2,%3},{%4,%5,%6,%7},{%8,%9},{%0,%1,%2,%3};\n"
        : "+f"(d[0]), "+f"(d[1]), "+f"(d[2]), "+f"(d[3])
        : "r"(a[0]), "r"(a[1]), "r"(a[2]), "r"(a[3]),
          "r"(b[0]), "r"(b[1]));
}

// ---------------- K0: reset per-call state ----------------
__global__ void init_kernel() {
    int i = blockIdx.x * blockDim.x + threadIdx.x;
    if (i < NEXP) g_counts[i] = 0;
    if (i < ROWCAP) {
        g_pair_tok[i] = -1;
        g_pair_wt[i]  = 0.0f;
    }
}

// ---------------- K1: router (one warp per token, fp64 accumulation) ----------------
__global__ void router_kernel(const float* __restrict__ x,
                              const float* __restrict__ rw,
                              const float* __restrict__ rb) {
    int warp = (blockIdx.x * blockDim.x + threadIdx.x) >> 5;
    if (warp >= T_TOK) return;
    int lane = threadIdx.x & 31;

    double acc[NEXP];
#pragma unroll
    for (int e = 0; e < NEXP; ++e) acc[e] = 0.0;

    const float* xr = x + (size_t)warp * HDIM;
    for (int h = lane; h < HDIM; h += 32) {
        double xv = (double)xr[h];
        const float* w = rw + h * NEXP;
#pragma unroll
        for (int e = 0; e < NEXP; ++e) acc[e] += xv * (double)w[e];
    }
#pragma unroll
    for (int off = 16; off; off >>= 1) {
#pragma unroll
        for (int e = 0; e < NEXP; ++e)
            acc[e] += __shfl_down_sync(0xffffffffu, acc[e], off);
    }
    if (lane == 0) {
        float lg[NEXP];
        float mx = -1e30f;
#pragma unroll
        for (int e = 0; e < NEXP; ++e) {
            lg[e] = (float)acc[e] + rb[e];
            mx = fmaxf(mx, lg[e]);
        }
        float p[NEXP];
        float s = 0.0f;
#pragma unroll
        for (int e = 0; e < NEXP; ++e) { p[e] = expf(lg[e] - mx); s += p[e]; }
        // top-2 (strict >, keeps lowest index on ties like lax.top_k)
        int i0 = 0;
#pragma unroll
        for (int e = 1; e < NEXP; ++e) if (p[e] > p[i0]) i0 = e;
        int i1 = (i0 == 0) ? 1 : 0;
#pragma unroll
        for (int e = 0; e < NEXP; ++e) if (e != i0 && p[e] > p[i1]) i1 = e;
        float w0 = p[i0], w1 = p[i1];
        float ws = w0 + w1;
        w0 /= ws; w1 /= ws;
        g_tok_eid[warp * 2 + 0] = i0;
        g_tok_eid[warp * 2 + 1] = i1;
        g_tok_w[warp * 2 + 0] = w0;
        g_tok_w[warp * 2 + 1] = w1;
        atomicAdd(&g_counts[i0], 1);
        atomicAdd(&g_counts[i1], 1);
    }
}

// ---------------- K2: plan (128-aligned per-expert segments) ----------------
__global__ void plan_kernel() {
    if (threadIdx.x == 0) {
        int off = 0, tix = 0;
        for (int e = 0; e < NEXP; ++e) {
            g_cursor[e] = off;
            int tiles = (g_counts[e] + BM - 1) / BM;
            for (int i = 0; i < tiles; ++i) g_tile_e[tix++] = e;
            off += tiles * BM;
        }
        g_num_tiles = tix;
    }
}

// ---------------- K3: scatter tokens into expert segments ----------------
__global__ void scatter_kernel() {
    int t = blockIdx.x * blockDim.x + threadIdx.x;
    if (t >= T_TOK) return;
#pragma unroll
    for (int k = 0; k < TOPK; ++k) {
        int e = g_tok_eid[t * 2 + k];
        int r = atomicAdd(&g_cursor[e], 1);
        g_pair_tok[r] = t;
        g_pair_wt[r]  = g_tok_w[t * 2 + k];
        g_row_of[t * 2 + k] = r;
    }
}

// ---------------- K4/K5: tiled TF32 tensor-core GEMM ----------------
// FFN1: C = gelu(gather(x) @ w1[e] + b1[e])      -> g_scr1   (N=4096, K=1024)
// FFN2: C = (g_scr1 @ w2[e] + b2[e]) * pair_wt   -> g_scr2   (N=1024, K=4096)
template <int NDIM, int KTOT, bool FFN1>
__global__ void __launch_bounds__(256)
moe_gemm(const float* __restrict__ Ain,
         const float* __restrict__ Wall,
         const float* __restrict__ biasAll) {
    const int mtile = blockIdx.y;
    if (mtile >= g_num_tiles) return;
    const int e  = g_tile_e[mtile];
    const int n0 = blockIdx.x * BN;

    const int tid  = threadIdx.x;
    const int lane = tid & 31;
    const int wid  = tid >> 5;
    const int wm   = wid >> 2;   // 0..1  (64-row warp slabs)
    const int wn   = wid & 3;    // 0..3  (32-col warp slabs)
    const int g    = lane >> 2;  // 0..7
    const int tig  = lane & 3;   // 0..3

    __shared__ __align__(16) float As[2][BM][BK + 4];  // stride 20 -> conflict-free frags
    __shared__ __align__(16) float Bs[2][BK][BN + 8];  // stride 136 -> conflict-free frags

    const float* W     = Wall + (size_t)e * KTOT * NDIM;
    const float* Abase = FFN1 ? Ain : (const float*)g_scr1;

    // A stage: 128x16 floats = 512 float4; 2 per thread
    const int aRow0 = tid >> 2;
    const int aRow1 = aRow0 + 64;
    const int aCol0 = (tid & 3) * 4;
    size_t asrc0, asrc1;
    if (FFN1) {
        int t0 = g_pair_tok[mtile * BM + aRow0]; if (t0 < 0) t0 = 0;
        int t1 = g_pair_tok[mtile * BM + aRow1]; if (t1 < 0) t1 = 0;
        asrc0 = (size_t)t0 * KTOT;
        asrc1 = (size_t)t1 * KTOT;
    } else {
        asrc0 = (size_t)(mtile * BM + aRow0) * KTOT;
        asrc1 = (size_t)(mtile * BM + aRow1) * KTOT;
    }
    // B stage: 16x128 floats = 512 float4; 2 per thread
    const int bRow0 = tid >> 5;
    const int bRow1 = bRow0 + 8;
    const int bCol0 = (lane) * 4;

    float c[4][4][4];
#pragma unroll
    for (int mi = 0; mi < 4; ++mi)
#pragma unroll
        for (int ni = 0; ni < 4; ++ni)
#pragma unroll
            for (int q = 0; q < 4; ++q) c[mi][ni][q] = 0.0f;

    float4 ra0, ra1, rb0, rb1;

    // prologue: load kt=0, store to buffer 0
    ra0 = *(const float4*)(Abase + asrc0 + aCol0);
    ra1 = *(const float4*)(Abase + asrc1 + aCol0);
    rb0 = *(const float4*)(W + (size_t)bRow0 * NDIM + n0 + bCol0);
    rb1 = *(const float4*)(W + (size_t)bRow1 * NDIM + n0 + bCol0);
    *(float4*)&As[0][aRow0][aCol0] = tf32x4(ra0);
    *(float4*)&As[0][aRow1][aCol0] = tf32x4(ra1);
    *(float4*)&Bs[0][bRow0][bCol0] = tf32x4(rb0);
    *(float4*)&Bs[0][bRow1][bCol0] = tf32x4(rb1);
    __syncthreads();

    const int NK = KTOT / BK;
    int buf = 0;
    for (int kt = 0; kt < NK; ++kt) {
        if (kt + 1 < NK) {
            const int k0 = (kt + 1) * BK;
            ra0 = *(const float4*)(Abase + asrc0 + k0 + aCol0);
            ra1 = *(const float4*)(Abase + asrc1 + k0 + aCol0);
            rb0 = *(const float4*)(W + (size_t)(k0 + bRow0) * NDIM + n0 + bCol0);
            rb1 = *(const float4*)(W + (size_t)(k0 + bRow1) * NDIM + n0 + bCol0);
        }
#pragma unroll
        for (int kk = 0; kk < BK; kk += 8) {
            uint32_t af[4][4];
            uint32_t bfr[4][2];
#pragma unroll
            for (int mi = 0; mi < 4; ++mi) {
                int r0 = wm * 64 + mi * 16;
                af[mi][0] = __float_as_uint(As[buf][r0 + g][kk + tig]);
                af[mi][1] = __float_as_uint(As[buf][r0 + g + 8][kk + tig]);
                af[mi][2] = __float_as_uint(As[buf][r0 + g][kk + tig + 4]);
                af[mi][3] = __float_as_uint(As[buf][r0 + g + 8][kk + tig + 4]);
            }
#pragma unroll
            for (int ni = 0; ni < 4; ++ni) {
                int cn = wn * 32 + ni * 8 + g;
                bfr[ni][0] = __float_as_uint(Bs[buf][kk + tig][cn]);
                bfr[ni][1] = __float_as_uint(Bs[buf][kk + tig + 4][cn]);
            }
#pragma unroll
            for (int mi = 0; mi < 4; ++mi)
#pragma unroll
                for (int ni = 0; ni < 4; ++ni)
                    mma_tf32(c[mi][ni], af[mi], bfr[ni]);
        }
        if (kt + 1 < NK) {
            int nb = buf ^ 1;
            *(float4*)&As[nb][aRow0][aCol0] = tf32x4(ra0);
            *(float4*)&As[nb][aRow1][aCol0] = tf32x4(ra1);
            *(float4*)&Bs[nb][bRow0][bCol0] = tf32x4(rb0);
            *(float4*)&Bs[nb][bRow1][bCol0] = tf32x4(rb1);
            __syncthreads();
            buf = nb;
        }
    }

    // epilogue
    const float* bias = biasAll + (size_t)e * NDIM;
    float* Cout = FFN1 ? g_scr1 : g_scr2;
#pragma unroll
    for (int mi = 0; mi < 4; ++mi) {
#pragma unroll
        for (int rr = 0; rr < 2; ++rr) {
            int rloc = wm * 64 + mi * 16 + g + rr * 8;
            int r    = mtile * BM + rloc;
            float wt = 1.0f;
            if (!FFN1) wt = g_pair_wt[r];
#pragma unroll
            for (int ni = 0; ni < 4; ++ni) {
                int col = n0 + wn * 32 + ni * 8 + tig * 2;
                float v0 = c[mi][ni][rr * 2 + 0] + bias[col];
                float v1 = c[mi][ni][rr * 2 + 1] + bias[col + 1];
                float2 st;
                if (FFN1) {
                    st.x = to_tf32(gelu_tanh(v0));   // pre-round for GEMM2 inputs
                    st.y = to_tf32(gelu_tanh(v1));
                } else {
                    st.x = v0 * wt;
                    st.y = v1 * wt;
                }
                *(float2*)&Cout[(size_t)r * NDIM + col] = st;
            }
        }
    }
}

// ---------------- K6: deterministic combine ----------------
__global__ void combine_kernel(float* __restrict__ out) {
    size_t idx = (size_t)blockIdx.x * blockDim.x + threadIdx.x;
    if (idx >= (size_t)T_TOK * HDIM) return;
    int t = (int)(idx >> 10);
    int h = (int)(idx & 1023);
    int r0 = g_row_of[t * 2 + 0];
    int r1 = g_row_of[t * 2 + 1];
    out[idx] = g_scr2[(size_t)r0 * HDIM + h] + g_scr2[(size_t)r1 * HDIM + h];
}

// ---------------- launch ----------------
extern "C" void kernel_launch(void* const* d_in, const int* in_sizes, int n_in,
                              void* d_out, int out_size) {
    const float* x  = (const float*)d_in[0];  // (B,S,H)
    const float* w1 = (const float*)d_in[1];  // (E,H,F)
    const float* b1 = (const float*)d_in[2];  // (E,F)
    const float* w2 = (const float*)d_in[3];  // (E,F,H)
    const float* b2 = (const float*)d_in[4];  // (E,H)
    const float* rw = (const float*)d_in[5];  // (H,E)
    const float* rb = (const float*)d_in[6];  // (E,)
    float* out = (float*)d_out;

    init_kernel<<<ROWCAP / 256, 256>>>();
    router_kernel<<<(T_TOK * 32) / 256, 256>>>(x, rw, rb);
    plan_kernel<<<1, 32>>>();
    scatter_kernel<<<T_TOK / 256, 256>>>();
    moe_gemm<FDIM, HDIM, true><<<dim3(FDIM / BN, MAXTILES), 256>>>(x, w1, b1);
    moe_gemm<HDIM, FDIM, false><<<dim3(HDIM / BN, MAXTILES), 256>>>(nullptr, w2, b2);
    combine_kernel<<<(T_TOK * HDIM) / 256, 256>>>(out);
}

// round 11
// speedup vs baseline: 1.0872x; 1.0872x over previous
#include <cuda_runtime.h>
#include <cstdint>
#include <math.h>

// ---------------- problem constants ----------------
#define T_TOK 8192
#define HDIM  1024
#define FDIM  4096
#define NEXP  8
#define TOPK  2

// ---------------- GEMM tiling ----------------
#define BM 128
#define BN 128
#define BK 16
#define MAXTILES 136
#define ROWCAP   (MAXTILES * BM)

// ---------------- scratch (static device globals; no allocs) ----------------
// NOTE: these symbols are ONLY referenced from device code. Passing them as
// kernel arguments from host code yields the host shadow address (garbage on
// device) — that was the R4/R6 failure mode.
__device__ float g_scr1[(size_t)ROWCAP * FDIM];
__device__ float g_scr2[(size_t)ROWCAP * HDIM];
__device__ float g_xr[(size_t)T_TOK * HDIM];          // tf32-rounded x
__device__ float g_w1r[(size_t)NEXP * HDIM * FDIM];   // tf32-rounded w1
__device__ float g_w2r[(size_t)NEXP * FDIM * HDIM];   // tf32-rounded w2
__device__ int   g_pair_tok[ROWCAP];
__device__ float g_pair_wt[ROWCAP];
__device__ int   g_row_of[T_TOK * TOPK];
__device__ int   g_tok_eid[T_TOK * TOPK];
__device__ float g_tok_w[T_TOK * TOPK];
__device__ int   g_counts[NEXP];
__device__ int   g_cursor[NEXP];
__device__ int   g_tile_e[MAXTILES];
__device__ int   g_num_tiles;

// ---------------- helpers ----------------
__device__ __forceinline__ float to_tf32(float x) {
    uint32_t u;
    asm("cvt.rna.tf32.f32 %0, %1;" : "=r"(u) : "f"(x));
    return __uint_as_float(u);
}

__device__ __forceinline__ float4 tf32x4(float4 v) {
    float4 r;
    r.x = to_tf32(v.x); r.y = to_tf32(v.y);
    r.z = to_tf32(v.z); r.w = to_tf32(v.w);
    return r;
}

__device__ __forceinline__ float gelu_tanh(float v) {
    // jax.nn.gelu approximate=True
    float u = v * (0.7978845608028654f + 0.03567740813636141f * v * v);
    return 0.5f * v * (1.0f + tanhf(u));
}

__device__ __forceinline__ void mma_tf32(float* d, const uint32_t* a, const uint32_t* b) {
    asm volatile(
        "mma.sync.aligned.m16n8k8.row.col.f32.tf32.tf32.f32 "
        "{%0,%1,%2,%3},{%4,%5,%6,%7},{%8,%9},{%0,%1,%2,%3};\n"
        : "+f"(d[0]), "+f"(d[1]), "+f"(d[2]), "+f"(d[3])
        : "r"(a[0]), "r"(a[1]), "r"(a[2]), "r"(a[3]),
          "r"(b[0]), "r"(b[1]));
}

// ---------------- K0: reset per-call state ----------------
__global__ void init_kernel() {
    int i = blockIdx.x * blockDim.x + threadIdx.x;
    if (i < NEXP) g_counts[i] = 0;
    if (i < ROWCAP) {
        g_pair_tok[i] = -1;
        g_pair_wt[i]  = 0.0f;
    }
}

// ---------------- K1: router (one warp per token, fp64 accumulation) ----------------
__global__ void router_kernel(const float* __restrict__ x,
                              const float* __restrict__ rw,
                              const float* __restrict__ rb) {
    int warp = (blockIdx.x * blockDim.x + threadIdx.x) >> 5;
    if (warp >= T_TOK) return;
    int lane = threadIdx.x & 31;

    double acc[NEXP];
#pragma unroll
    for (int e = 0; e < NEXP; ++e) acc[e] = 0.0;

    const float* xr = x + (size_t)warp * HDIM;
    for (int h = lane; h < HDIM; h += 32) {
        double xv = (double)xr[h];
        const float* w = rw + h * NEXP;
#pragma unroll
        for (int e = 0; e < NEXP; ++e) acc[e] += xv * (double)w[e];
    }
#pragma unroll
    for (int off = 16; off; off >>= 1) {
#pragma unroll
        for (int e = 0; e < NEXP; ++e)
            acc[e] += __shfl_down_sync(0xffffffffu, acc[e], off);
    }
    if (lane == 0) {
        float lg[NEXP];
        float mx = -1e30f;
#pragma unroll
        for (int e = 0; e < NEXP; ++e) {
            lg[e] = (float)acc[e] + rb[e];
            mx = fmaxf(mx, lg[e]);
        }
        float p[NEXP];
        float s = 0.0f;
#pragma unroll
        for (int e = 0; e < NEXP; ++e) { p[e] = expf(lg[e] - mx); s += p[e]; }
        int i0 = 0;
#pragma unroll
        for (int e = 1; e < NEXP; ++e) if (p[e] > p[i0]) i0 = e;
        int i1 = (i0 == 0) ? 1 : 0;
#pragma unroll
        for (int e = 0; e < NEXP; ++e) if (e != i0 && p[e] > p[i1]) i1 = e;
        float w0 = p[i0], w1 = p[i1];
        float ws = w0 + w1;
        w0 /= ws; w1 /= ws;
        g_tok_eid[warp * 2 + 0] = i0;
        g_tok_eid[warp * 2 + 1] = i1;
        g_tok_w[warp * 2 + 0] = w0;
        g_tok_w[warp * 2 + 1] = w1;
        atomicAdd(&g_counts[i0], 1);
        atomicAdd(&g_counts[i1], 1);
    }
}

// ---------------- K2: plan ----------------
__global__ void plan_kernel() {
    if (threadIdx.x == 0) {
        int off = 0, tix = 0;
        for (int e = 0; e < NEXP; ++e) {
            g_cursor[e] = off;
            int tiles = (g_counts[e] + BM - 1) / BM;
            for (int i = 0; i < tiles; ++i) g_tile_e[tix++] = e;
            off += tiles * BM;
        }
        g_num_tiles = tix;
    }
}

// ---------------- K3: scatter ----------------
__global__ void scatter_kernel() {
    int t = blockIdx.x * blockDim.x + threadIdx.x;
    if (t >= T_TOK) return;
#pragma unroll
    for (int k = 0; k < TOPK; ++k) {
        int e = g_tok_eid[t * 2 + k];
        int r = atomicAdd(&g_cursor[e], 1);
        g_pair_tok[r] = t;
        g_pair_wt[r]  = g_tok_w[t * 2 + k];
        g_row_of[t * 2 + k] = r;
    }
}

// ---------------- K4: elementwise RNA-tf32 rounding ----------------
// dst selected by template in DEVICE code (0=g_xr, 1=g_w1r, 2=g_w2r).
template <int WHICH>
__global__ void round_tf32_kernel(const float* __restrict__ src, int n4) {
    int i = blockIdx.x * blockDim.x + threadIdx.x;
    if (i >= n4) return;
    float* dst = (WHICH == 0) ? g_xr : (WHICH == 1) ? g_w1r : g_w2r;
    ((float4*)dst)[i] = tf32x4(((const float4*)src)[i]);
}

// ---------------- K5/K6: tiled TF32 tensor-core GEMM ----------------
// CTA 128x128, 4 warps of 64x64, BK=16, register-staged double buffer,
// static smem (37.9 KB) -> 2 CTAs/SM. All scratch pointers resolved in
// device code from the FFN1 template flag.
// FFN1: scr1 = tf32(gelu(gather(g_xr) @ g_w1r + b1))  (NDIM=F, KTOT=H)
// FFN2: scr2 = wt * (g_scr1 @ g_w2r + b2)             (NDIM=H, KTOT=F)
template <int NDIM, int KTOT, bool FFN1>
__global__ void __launch_bounds__(128, 2)
moe_gemm(const float* __restrict__ biasAll) {
    const int mtile = blockIdx.y;
    if (mtile >= g_num_tiles) return;
    const int e  = g_tile_e[mtile];
    const int n0 = blockIdx.x * BN;

    const int tid  = threadIdx.x;
    const int lane = tid & 31;
    const int wid  = tid >> 5;     // 0..3
    const int wm   = wid >> 1;     // 0..1  (64-row slab)
    const int wn   = wid & 1;      // 0..1  (64-col slab)
    const int g    = lane >> 2;    // 0..7
    const int tig  = lane & 3;     // 0..3

    __shared__ __align__(16) float As[2][BM][BK + 4];   // stride 20: conflict-free
    __shared__ __align__(16) float Bs[2][BK][BN + 8];   // stride 136: conflict-free

    const float* Ain = FFN1 ? (const float*)g_xr  : (const float*)g_scr1;
    const float* Wr  = FFN1 ? (const float*)g_w1r : (const float*)g_w2r;
    const float* W   = Wr + (size_t)e * KTOT * NDIM;    // [K][N] row-major

    // ---- staging addresses: A 512 float4 -> 4/thread; B 512 float4 -> 4/thread
    size_t a_src[4];
    int    a_row[4], a_q[4];
#pragma unroll
    for (int i = 0; i < 4; ++i) {
        int idx = i * 128 + tid;
        a_row[i] = idx >> 2;            // 0..127
        a_q[i]   = (idx & 3) * 4;       // 0,4,8,12
        size_t srow;
        if (FFN1) {
            int t = g_pair_tok[mtile * BM + a_row[i]];
            if (t < 0) t = 0;
            srow = (size_t)t * KTOT;
        } else {
            srow = (size_t)(mtile * BM + a_row[i]) * KTOT;
        }
        a_src[i] = srow + a_q[i];
    }
    int b_row[4], b_q[4];
#pragma unroll
    for (int i = 0; i < 4; ++i) {
        int idx = i * 128 + tid;
        b_row[i] = idx >> 5;            // 0..15
        b_q[i]   = (idx & 31) * 4;      // 0..124
    }

    float c[4][8][4];
#pragma unroll
    for (int mi = 0; mi < 4; ++mi)
#pragma unroll
        for (int ni = 0; ni < 8; ++ni)
#pragma unroll
            for (int q = 0; q < 4; ++q) c[mi][ni][q] = 0.0f;

    float4 ra[4], rb[4];

    // prologue: load chunk 0 into buffer 0
#pragma unroll
    for (int i = 0; i < 4; ++i) ra[i] = *(const float4*)(Ain + a_src[i]);
#pragma unroll
    for (int i = 0; i < 4; ++i)
        rb[i] = *(const float4*)(W + (size_t)b_row[i] * NDIM + n0 + b_q[i]);
#pragma unroll
    for (int i = 0; i < 4; ++i) *(float4*)&As[0][a_row[i]][a_q[i]] = ra[i];
#pragma unroll
    for (int i = 0; i < 4; ++i) *(float4*)&Bs[0][b_row[i]][b_q[i]] = rb[i];
    __syncthreads();

    const int NK = KTOT / BK;
    int buf = 0;
    for (int kt = 0; kt < NK; ++kt) {
        if (kt + 1 < NK) {
            const int k0 = (kt + 1) * BK;
#pragma unroll
            for (int i = 0; i < 4; ++i)
                ra[i] = *(const float4*)(Ain + a_src[i] + k0);
#pragma unroll
            for (int i = 0; i < 4; ++i)
                rb[i] = *(const float4*)(W + (size_t)(k0 + b_row[i]) * NDIM + n0 + b_q[i]);
        }
#pragma unroll
        for (int kk = 0; kk < BK; kk += 8) {
            uint32_t af[4][4], bf[8][2];
#pragma unroll
            for (int mi = 0; mi < 4; ++mi) {
                int rA = wm * 64 + mi * 16 + g;
                af[mi][0] = __float_as_uint(As[buf][rA][kk + tig]);
                af[mi][1] = __float_as_uint(As[buf][rA + 8][kk + tig]);
                af[mi][2] = __float_as_uint(As[buf][rA][kk + tig + 4]);
                af[mi][3] = __float_as_uint(As[buf][rA + 8][kk + tig + 4]);
            }
#pragma unroll
            for (int ni = 0; ni < 8; ++ni) {
                int cn = wn * 64 + ni * 8 + g;
                bf[ni][0] = __float_as_uint(Bs[buf][kk + tig][cn]);
                bf[ni][1] = __float_as_uint(Bs[buf][kk + tig + 4][cn]);
            }
#pragma unroll
            for (int mi = 0; mi < 4; ++mi)
#pragma unroll
                for (int ni = 0; ni < 8; ++ni)
                    mma_tf32(c[mi][ni], af[mi], bf[ni]);
        }
        if (kt + 1 < NK) {
            int nb = buf ^ 1;
#pragma unroll
            for (int i = 0; i < 4; ++i) *(float4*)&As[nb][a_row[i]][a_q[i]] = ra[i];
#pragma unroll
            for (int i = 0; i < 4; ++i) *(float4*)&Bs[nb][b_row[i]][b_q[i]] = rb[i];
            __syncthreads();
            buf = nb;
        }
    }

    // ---- epilogue ----
    const float* bias = biasAll + (size_t)e * NDIM + n0;
    float* Cout = FFN1 ? (float*)g_scr1 : (float*)g_scr2;
#pragma unroll
    for (int mi = 0; mi < 4; ++mi) {
        size_t r0 = (size_t)mtile * BM + wm * 64 + mi * 16 + g;
        float w0 = 1.0f, w1 = 1.0f;
        if (!FFN1) {
            w0 = g_pair_wt[r0];
            w1 = g_pair_wt[r0 + 8];
        }
#pragma unroll
        for (int ni = 0; ni < 8; ++ni) {
            int col = wn * 64 + ni * 8 + tig * 2;
            float b0 = bias[col], b1v = bias[col + 1];
            float v0 = c[mi][ni][0] + b0, v1 = c[mi][ni][1] + b1v;   // row g
            float v2 = c[mi][ni][2] + b0, v3 = c[mi][ni][3] + b1v;   // row g+8
            float2 s0, s1;
            if (FFN1) {
                s0.x = to_tf32(gelu_tanh(v0)); s0.y = to_tf32(gelu_tanh(v1));
                s1.x = to_tf32(gelu_tanh(v2)); s1.y = to_tf32(gelu_tanh(v3));
            } else {
                s0.x = v0 * w0; s0.y = v1 * w0;
                s1.x = v2 * w1; s1.y = v3 * w1;
            }
            *(float2*)&Cout[r0 * NDIM + n0 + col] = s0;
            *(float2*)&Cout[(r0 + 8) * NDIM + n0 + col] = s1;
        }
    }
}

// ---------------- K7: deterministic combine ----------------
__global__ void combine_kernel(float* __restrict__ out) {
    int idx = blockIdx.x * blockDim.x + threadIdx.x;   // over T_TOK * HDIM / 4
    int t  = idx / (HDIM / 4);
    int h4 = idx % (HDIM / 4);
    if (t >= T_TOK) return;
    size_t r0 = (size_t)g_row_of[t * 2 + 0];
    size_t r1 = (size_t)g_row_of[t * 2 + 1];
    float4 a = *(const float4*)&g_scr2[r0 * HDIM + h4 * 4];
    float4 b = *(const float4*)&g_scr2[r1 * HDIM + h4 * 4];
    float4 o;
    o.x = a.x + b.x; o.y = a.y + b.y; o.z = a.z + b.z; o.w = a.w + b.w;
    *(float4*)&out[(size_t)t * HDIM + h4 * 4] = o;
}

// ---------------- launch ----------------
extern "C" void kernel_launch(void* const* d_in, const int* in_sizes, int n_in,
                              void* d_out, int out_size) {
    const float* x  = (const float*)d_in[0];  // (B,S,H)
    const float* w1 = (const float*)d_in[1];  // (E,H,F)
    const float* b1 = (const float*)d_in[2];  // (E,F)
    const float* w2 = (const float*)d_in[3];  // (E,F,H)
    const float* b2 = (const float*)d_in[4];  // (E,H)
    const float* rw = (const float*)d_in[5];  // (H,E)
    const float* rb = (const float*)d_in[6];  // (E,)
    float* out = (float*)d_out;

    init_kernel<<<ROWCAP / 256, 256>>>();
    router_kernel<<<(T_TOK * 32) / 256, 256>>>(x, rw, rb);
    plan_kernel<<<1, 32>>>();
    scatter_kernel<<<T_TOK / 256, 256>>>();

    // RNA-tf32 pre-rounding (so HMMA's RZ truncation is a no-op).
    // Destinations are device symbols selected INSIDE the kernels.
    {
        int n4x = T_TOK * HDIM / 4;
        int n4w = NEXP * HDIM * FDIM / 4;
        round_tf32_kernel<0><<<(n4x + 255) / 256, 256>>>(x, n4x);
        round_tf32_kernel<1><<<(n4w + 255) / 256, 256>>>(w1, n4w);
        round_tf32_kernel<2><<<(n4w + 255) / 256, 256>>>(w2, n4w);
    }

    moe_gemm<FDIM, HDIM, true><<<dim3(FDIM / BN, MAXTILES), 128>>>(b1);
    moe_gemm<HDIM, FDIM, false><<<dim3(HDIM / BN, MAXTILES), 128>>>(b2);

    combine_kernel<<<(T_TOK * HDIM / 4 + 255) / 256, 256>>>(out);
}

// round 12
// speedup vs baseline: 1.0923x; 1.0047x over previous
#include <cuda_runtime.h>
#include <cstdint>
#include <math.h>

// ---------------- problem constants ----------------
#define T_TOK 8192
#define HDIM  1024
#define FDIM  4096
#define NEXP  8
#define TOPK  2

// ---------------- GEMM tiling ----------------
#define BM 128
#define BN 128
#define BK 16
#define MAXTILES 136
#define ROWCAP   (MAXTILES * BM)

// ---------------- scratch (static device globals; no allocs) ----------------
// NOTE: referenced ONLY from device code (host-passed __device__ symbols decay
// to the host shadow address — the R4/R6 failure mode).
__device__ float g_scr1[(size_t)ROWCAP * FDIM];
__device__ float g_scr2[(size_t)ROWCAP * HDIM];
__device__ int   g_pair_tok[ROWCAP];
__device__ float g_pair_wt[ROWCAP];
__device__ int   g_row_of[T_TOK * TOPK];
__device__ int   g_tok_eid[T_TOK * TOPK];
__device__ float g_tok_w[T_TOK * TOPK];
__device__ int   g_counts[NEXP];
__device__ int   g_cursor[NEXP];
__device__ int   g_tile_e[MAXTILES];
__device__ int   g_num_tiles;

// ---------------- helpers ----------------
__device__ __forceinline__ float to_tf32(float x) {
    uint32_t u;
    asm("cvt.rna.tf32.f32 %0, %1;" : "=r"(u) : "f"(x));
    return __uint_as_float(u);
}

__device__ __forceinline__ float4 tf32x4(float4 v) {
    float4 r;
    r.x = to_tf32(v.x); r.y = to_tf32(v.y);
    r.z = to_tf32(v.z); r.w = to_tf32(v.w);
    return r;
}

__device__ __forceinline__ float gelu_tanh(float v) {
    // jax.nn.gelu approximate=True
    float u = v * (0.7978845608028654f + 0.03567740813636141f * v * v);
    return 0.5f * v * (1.0f + tanhf(u));
}

__device__ __forceinline__ void mma_tf32(float* d, const uint32_t* a, const uint32_t* b) {
    asm volatile(
        "mma.sync.aligned.m16n8k8.row.col.f32.tf32.tf32.f32 "
        "{%0,%1,%2,%3},{%4,%5,%6,%7},{%8,%9},{%0,%1,%2,%3};\n"
        : "+f"(d[0]), "+f"(d[1]), "+f"(d[2]), "+f"(d[3])
        : "r"(a[0]), "r"(a[1]), "r"(a[2]), "r"(a[3]),
          "r"(b[0]), "r"(b[1]));
}

// ---------------- K0: reset per-call state ----------------
__global__ void init_kernel() {
    int i = blockIdx.x * blockDim.x + threadIdx.x;
    if (i < NEXP) g_counts[i] = 0;
    if (i < ROWCAP) {
        g_pair_tok[i] = -1;
        g_pair_wt[i]  = 0.0f;
    }
}

// ---------------- K1: router (one warp per token, fp64 accumulation) ----------------
__global__ void router_kernel(const float* __restrict__ x,
                              const float* __restrict__ rw,
                              const float* __restrict__ rb) {
    int warp = (blockIdx.x * blockDim.x + threadIdx.x) >> 5;
    if (warp >= T_TOK) return;
    int lane = threadIdx.x & 31;

    double acc[NEXP];
#pragma unroll
    for (int e = 0; e < NEXP; ++e) acc[e] = 0.0;

    const float* xr = x + (size_t)warp * HDIM;
    for (int h = lane; h < HDIM; h += 32) {
        double xv = (double)xr[h];
        const float* w = rw + h * NEXP;
#pragma unroll
        for (int e = 0; e < NEXP; ++e) acc[e] += xv * (double)w[e];
    }
#pragma unroll
    for (int off = 16; off; off >>= 1) {
#pragma unroll
        for (int e = 0; e < NEXP; ++e)
            acc[e] += __shfl_down_sync(0xffffffffu, acc[e], off);
    }
    if (lane == 0) {
        float lg[NEXP];
        float mx = -1e30f;
#pragma unroll
        for (int e = 0; e < NEXP; ++e) {
            lg[e] = (float)acc[e] + rb[e];
            mx = fmaxf(mx, lg[e]);
        }
        float p[NEXP];
        float s = 0.0f;
#pragma unroll
        for (int e = 0; e < NEXP; ++e) { p[e] = expf(lg[e] - mx); s += p[e]; }
        int i0 = 0;
#pragma unroll
        for (int e = 1; e < NEXP; ++e) if (p[e] > p[i0]) i0 = e;
        int i1 = (i0 == 0) ? 1 : 0;
#pragma unroll
        for (int e = 0; e < NEXP; ++e) if (e != i0 && p[e] > p[i1]) i1 = e;
        float w0 = p[i0], w1 = p[i1];
        float ws = w0 + w1;
        w0 /= ws; w1 /= ws;
        g_tok_eid[warp * 2 + 0] = i0;
        g_tok_eid[warp * 2 + 1] = i1;
        g_tok_w[warp * 2 + 0] = w0;
        g_tok_w[warp * 2 + 1] = w1;
        atomicAdd(&g_counts[i0], 1);
        atomicAdd(&g_counts[i1], 1);
    }
}

// ---------------- K2: plan ----------------
__global__ void plan_kernel() {
    if (threadIdx.x == 0) {
        int off = 0, tix = 0;
        for (int e = 0; e < NEXP; ++e) {
            g_cursor[e] = off;
            int tiles = (g_counts[e] + BM - 1) / BM;
            for (int i = 0; i < tiles; ++i) g_tile_e[tix++] = e;
            off += tiles * BM;
        }
        g_num_tiles = tix;
    }
}

// ---------------- K3: scatter ----------------
__global__ void scatter_kernel() {
    int t = blockIdx.x * blockDim.x + threadIdx.x;
    if (t >= T_TOK) return;
#pragma unroll
    for (int k = 0; k < TOPK; ++k) {
        int e = g_tok_eid[t * 2 + k];
        int r = atomicAdd(&g_cursor[e], 1);
        g_pair_tok[r] = t;
        g_pair_wt[r]  = g_tok_w[t * 2 + k];
        g_row_of[t * 2 + k] = r;
    }
}

// ---------------- K4/K5: tiled TF32 tensor-core GEMM ----------------
// CTA 128x128, 4 warps of 64x64, BK=16, register-staged double buffer,
// static smem (37.9 KB) -> 2 CTAs/SM. RNA-tf32 rounding fused into the
// smem-store path (rides the idle fma pipe; GEMM is MMA-pipe bound).
// FFN1: scr1 = tf32(gelu(gather(x) @ w1 + b1))   (NDIM=F, KTOT=H)
// FFN2: scr2 = wt * (g_scr1 @ w2 + b2)           (NDIM=H, KTOT=F)
// Ain/Wall are harness device pointers (safe as args); scratch resolved in
// device code from the FFN1 template flag.
template <int NDIM, int KTOT, bool FFN1>
__global__ void __launch_bounds__(128, 2)
moe_gemm(const float* __restrict__ AinArg,
         const float* __restrict__ Wall,
         const float* __restrict__ biasAll) {
    const int mtile = blockIdx.y;
    if (mtile >= g_num_tiles) return;
    const int e  = g_tile_e[mtile];
    const int n0 = blockIdx.x * BN;

    const int tid  = threadIdx.x;
    const int lane = tid & 31;
    const int wid  = tid >> 5;     // 0..3
    const int wm   = wid >> 1;     // 0..1  (64-row slab)
    const int wn   = wid & 1;      // 0..1  (64-col slab)
    const int g    = lane >> 2;    // 0..7
    const int tig  = lane & 3;     // 0..3

    __shared__ __align__(16) float As[2][BM][BK + 4];   // stride 20: conflict-free
    __shared__ __align__(16) float Bs[2][BK][BN + 8];   // stride 136: conflict-free

    const float* Ain = FFN1 ? AinArg : (const float*)g_scr1;
    const float* W   = Wall + (size_t)e * KTOT * NDIM;  // [K][N] row-major

    // ---- staging addresses: A 512 float4 -> 4/thread; B 512 float4 -> 4/thread
    size_t a_src[4];
    int    a_row[4], a_q[4];
#pragma unroll
    for (int i = 0; i < 4; ++i) {
        int idx = i * 128 + tid;
        a_row[i] = idx >> 2;            // 0..127
        a_q[i]   = (idx & 3) * 4;       // 0,4,8,12
        size_t srow;
        if (FFN1) {
            int t = g_pair_tok[mtile * BM + a_row[i]];
            if (t < 0) t = 0;
            srow = (size_t)t * KTOT;
        } else {
            srow = (size_t)(mtile * BM + a_row[i]) * KTOT;
        }
        a_src[i] = srow + a_q[i];
    }
    int b_row[4], b_q[4];
#pragma unroll
    for (int i = 0; i < 4; ++i) {
        int idx = i * 128 + tid;
        b_row[i] = idx >> 5;            // 0..15
        b_q[i]   = (idx & 31) * 4;      // 0..124
    }

    float c[4][8][4];
#pragma unroll
    for (int mi = 0; mi < 4; ++mi)
#pragma unroll
        for (int ni = 0; ni < 8; ++ni)
#pragma unroll
            for (int q = 0; q < 4; ++q) c[mi][ni][q] = 0.0f;

    float4 ra[4], rb[4];

    // prologue: load chunk 0 into buffer 0.
    // A: FFN1 needs RNA rounding (raw x); FFN2's A (g_scr1) is pre-rounded in
    // the FFN1 epilogue. B (raw w1/w2) always needs rounding.
#pragma unroll
    for (int i = 0; i < 4; ++i) ra[i] = *(const float4*)(Ain + a_src[i]);
#pragma unroll
    for (int i = 0; i < 4; ++i)
        rb[i] = *(const float4*)(W + (size_t)b_row[i] * NDIM + n0 + b_q[i]);
#pragma unroll
    for (int i = 0; i < 4; ++i)
        *(float4*)&As[0][a_row[i]][a_q[i]] = FFN1 ? tf32x4(ra[i]) : ra[i];
#pragma unroll
    for (int i = 0; i < 4; ++i) *(float4*)&Bs[0][b_row[i]][b_q[i]] = tf32x4(rb[i]);
    __syncthreads();

    const int NK = KTOT / BK;
    int buf = 0;
    for (int kt = 0; kt < NK; ++kt) {
        if (kt + 1 < NK) {
            const int k0 = (kt + 1) * BK;
#pragma unroll
            for (int i = 0; i < 4; ++i)
                ra[i] = *(const float4*)(Ain + a_src[i] + k0);
#pragma unroll
            for (int i = 0; i < 4; ++i)
                rb[i] = *(const float4*)(W + (size_t)(k0 + b_row[i]) * NDIM + n0 + b_q[i]);
        }
#pragma unroll
        for (int kk = 0; kk < BK; kk += 8) {
            uint32_t af[4][4], bf[8][2];
#pragma unroll
            for (int mi = 0; mi < 4; ++mi) {
                int rA = wm * 64 + mi * 16 + g;
                af[mi][0] = __float_as_uint(As[buf][rA][kk + tig]);
                af[mi][1] = __float_as_uint(As[buf][rA + 8][kk + tig]);
                af[mi][2] = __float_as_uint(As[buf][rA][kk + tig + 4]);
                af[mi][3] = __float_as_uint(As[buf][rA + 8][kk + tig + 4]);
            }
#pragma unroll
            for (int ni = 0; ni < 8; ++ni) {
                int cn = wn * 64 + ni * 8 + g;
                bf[ni][0] = __float_as_uint(Bs[buf][kk + tig][cn]);
                bf[ni][1] = __float_as_uint(Bs[buf][kk + tig + 4][cn]);
            }
#pragma unroll
            for (int mi = 0; mi < 4; ++mi)
#pragma unroll
                for (int ni = 0; ni < 8; ++ni)
                    mma_tf32(c[mi][ni], af[mi], bf[ni]);
        }
        if (kt + 1 < NK) {
            int nb = buf ^ 1;
#pragma unroll
            for (int i = 0; i < 4; ++i)
                *(float4*)&As[nb][a_row[i]][a_q[i]] = FFN1 ? tf32x4(ra[i]) : ra[i];
#pragma unroll
            for (int i = 0; i < 4; ++i) *(float4*)&Bs[nb][b_row[i]][b_q[i]] = tf32x4(rb[i]);
            __syncthreads();
            buf = nb;
        }
    }

    // ---- epilogue ----
    const float* bias = biasAll + (size_t)e * NDIM + n0;
    float* Cout = FFN1 ? (float*)g_scr1 : (float*)g_scr2;
#pragma unroll
    for (int mi = 0; mi < 4; ++mi) {
        size_t r0 = (size_t)mtile * BM + wm * 64 + mi * 16 + g;
        float w0 = 1.0f, w1 = 1.0f;
        if (!FFN1) {
            w0 = g_pair_wt[r0];
            w1 = g_pair_wt[r0 + 8];
        }
#pragma unroll
        for (int ni = 0; ni < 8; ++ni) {
            int col = wn * 64 + ni * 8 + tig * 2;
            float b0 = bias[col], b1v = bias[col + 1];
            float v0 = c[mi][ni][0] + b0, v1 = c[mi][ni][1] + b1v;   // row g
            float v2 = c[mi][ni][2] + b0, v3 = c[mi][ni][3] + b1v;   // row g+8
            float2 s0, s1;
            if (FFN1) {
                s0.x = to_tf32(gelu_tanh(v0)); s0.y = to_tf32(gelu_tanh(v1));
                s1.x = to_tf32(gelu_tanh(v2)); s1.y = to_tf32(gelu_tanh(v3));
            } else {
                s0.x = v0 * w0; s0.y = v1 * w0;
                s1.x = v2 * w1; s1.y = v3 * w1;
            }
            *(float2*)&Cout[r0 * NDIM + n0 + col] = s0;
            *(float2*)&Cout[(r0 + 8) * NDIM + n0 + col] = s1;
        }
    }
}

// ---------------- K6: deterministic combine ----------------
__global__ void combine_kernel(float* __restrict__ out) {
    int idx = blockIdx.x * blockDim.x + threadIdx.x;   // over T_TOK * HDIM / 4
    int t  = idx / (HDIM / 4);
    int h4 = idx % (HDIM / 4);
    if (t >= T_TOK) return;
    size_t r0 = (size_t)g_row_of[t * 2 + 0];
    size_t r1 = (size_t)g_row_of[t * 2 + 1];
    float4 a = *(const float4*)&g_scr2[r0 * HDIM + h4 * 4];
    float4 b = *(const float4*)&g_scr2[r1 * HDIM + h4 * 4];
    float4 o;
    o.x = a.x + b.x; o.y = a.y + b.y; o.z = a.z + b.z; o.w = a.w + b.w;
    *(float4*)&out[(size_t)t * HDIM + h4 * 4] = o;
}

// ---------------- launch ----------------
extern "C" void kernel_launch(void* const* d_in, const int* in_sizes, int n_in,
                              void* d_out, int out_size) {
    const float* x  = (const float*)d_in[0];  // (B,S,H)
    const float* w1 = (const float*)d_in[1];  // (E,H,F)
    const float* b1 = (const float*)d_in[2];  // (E,F)
    const float* w2 = (const float*)d_in[3];  // (E,F,H)
    const float* b2 = (const float*)d_in[4];  // (E,H)
    const float* rw = (const float*)d_in[5];  // (H,E)
    const float* rb = (const float*)d_in[6];  // (E,)
    float* out = (float*)d_out;

    init_kernel<<<ROWCAP / 256, 256>>>();                       // launch 1
    router_kernel<<<(T_TOK * 32) / 256, 256>>>(x, rw, rb);      // launch 2
    plan_kernel<<<1, 32>>>();                                   // launch 3
    scatter_kernel<<<T_TOK / 256, 256>>>();                     // launch 4

    moe_gemm<FDIM, HDIM, true><<<dim3(FDIM / BN, MAXTILES), 128>>>(x, w1, b1);        // launch 5
    moe_gemm<HDIM, FDIM, false><<<dim3(HDIM / BN, MAXTILES), 128>>>(nullptr, w2, b2); // launch 6 (ncu -s 5 captures this)

    combine_kernel<<<(T_TOK * HDIM / 4 + 255) / 256, 256>>>(out);                     // launch 7
}

// round 13
// speedup vs baseline: 1.5318x; 1.4024x over previous
#include <cuda_runtime.h>
#include <cuda_fp16.h>
#include <cstdint>
#include <math.h>

// ---------------- problem constants ----------------
#define T_TOK 8192
#define HDIM  1024
#define FDIM  4096
#define NEXP  8
#define TOPK  2

// ---------------- GEMM tiling ----------------
#define BM 128
#define BN 128
#define BK 32
#define MAXTILES 136
#define ROWCAP   (MAXTILES * BM)

#define A_PAD 8     // halves; row = 40 halves = 80 B
#define B_PAD 8     // halves; row = 136 halves = 272 B
#define ABUF_BYTES (BM * (BK + A_PAD) * 2)   // 10240
#define BBUF_BYTES (BK * (BN + B_PAD) * 2)   // 8704

// ---------------- scratch (static device globals; no allocs) ----------------
// Referenced ONLY from device code (host-passed __device__ symbols decay to
// the host shadow address — the R4/R6 failure mode).
__device__ __half g_scr1h[(size_t)ROWCAP * FDIM];   // fp16 gelu(x@w1+b1)
__device__ float  g_scr2[(size_t)ROWCAP * HDIM];
__device__ int    g_pair_tok[ROWCAP];
__device__ float  g_pair_wt[ROWCAP];
__device__ int    g_row_of[T_TOK * TOPK];
__device__ int    g_tok_eid[T_TOK * TOPK];
__device__ float  g_tok_w[T_TOK * TOPK];
__device__ int    g_counts[NEXP];
__device__ int    g_cursor[NEXP];
__device__ int    g_tile_e[MAXTILES];
__device__ int    g_num_tiles;

// ---------------- helpers ----------------
__device__ __forceinline__ uint32_t smem_to_u32(const void* p) {
    uint32_t a;
    asm("{ .reg .u64 t; cvta.to.shared.u64 t, %1; cvt.u32.u64 %0, t; }" : "=r"(a) : "l"(p));
    return a;
}

__device__ __forceinline__ uint2 f4h4(float4 v) {
    __half2 p0 = __floats2half2_rn(v.x, v.y);
    __half2 p1 = __floats2half2_rn(v.z, v.w);
    uint2 r;
    r.x = *(uint32_t*)&p0;
    r.y = *(uint32_t*)&p1;
    return r;
}

__device__ __forceinline__ float gelu_tanh(float v) {
    // jax.nn.gelu approximate=True
    float u = v * (0.7978845608028654f + 0.03567740813636141f * v * v);
    return 0.5f * v * (1.0f + tanhf(u));
}

__device__ __forceinline__ void ldsm_x4(uint32_t* r, uint32_t addr) {
    asm volatile("ldmatrix.sync.aligned.m8n8.x4.shared.b16 {%0,%1,%2,%3}, [%4];"
        : "=r"(r[0]), "=r"(r[1]), "=r"(r[2]), "=r"(r[3]) : "r"(addr));
}

__device__ __forceinline__ void ldsm_x4_t(uint32_t* r, uint32_t addr) {
    asm volatile("ldmatrix.sync.aligned.m8n8.x4.trans.shared.b16 {%0,%1,%2,%3}, [%4];"
        : "=r"(r[0]), "=r"(r[1]), "=r"(r[2]), "=r"(r[3]) : "r"(addr));
}

__device__ __forceinline__ void mma_f16(float* d, const uint32_t* a, const uint32_t* b) {
    asm volatile(
        "mma.sync.aligned.m16n8k16.row.col.f32.f16.f16.f32 "
        "{%0,%1,%2,%3},{%4,%5,%6,%7},{%8,%9},{%0,%1,%2,%3};\n"
        : "+f"(d[0]), "+f"(d[1]), "+f"(d[2]), "+f"(d[3])
        : "r"(a[0]), "r"(a[1]), "r"(a[2]), "r"(a[3]),
          "r"(b[0]), "r"(b[1]));
}

// ---------------- K0: reset per-call state ----------------
__global__ void init_kernel() {
    int i = blockIdx.x * blockDim.x + threadIdx.x;
    if (i < NEXP) g_counts[i] = 0;
    if (i < ROWCAP) {
        g_pair_tok[i] = -1;
        g_pair_wt[i]  = 0.0f;
    }
}

// ---------------- K1: router (one warp per token, fp64 accumulation) ----------------
__global__ void router_kernel(const float* __restrict__ x,
                              const float* __restrict__ rw,
                              const float* __restrict__ rb) {
    int warp = (blockIdx.x * blockDim.x + threadIdx.x) >> 5;
    if (warp >= T_TOK) return;
    int lane = threadIdx.x & 31;

    double acc[NEXP];
#pragma unroll
    for (int e = 0; e < NEXP; ++e) acc[e] = 0.0;

    const float* xr = x + (size_t)warp * HDIM;
    for (int h = lane; h < HDIM; h += 32) {
        double xv = (double)xr[h];
        const float* w = rw + h * NEXP;
#pragma unroll
        for (int e = 0; e < NEXP; ++e) acc[e] += xv * (double)w[e];
    }
#pragma unroll
    for (int off = 16; off; off >>= 1) {
#pragma unroll
        for (int e = 0; e < NEXP; ++e)
            acc[e] += __shfl_down_sync(0xffffffffu, acc[e], off);
    }
    if (lane == 0) {
        float lg[NEXP];
        float mx = -1e30f;
#pragma unroll
        for (int e = 0; e < NEXP; ++e) {
            lg[e] = (float)acc[e] + rb[e];
            mx = fmaxf(mx, lg[e]);
        }
        float p[NEXP];
        float s = 0.0f;
#pragma unroll
        for (int e = 0; e < NEXP; ++e) { p[e] = expf(lg[e] - mx); s += p[e]; }
        int i0 = 0;
#pragma unroll
        for (int e = 1; e < NEXP; ++e) if (p[e] > p[i0]) i0 = e;
        int i1 = (i0 == 0) ? 1 : 0;
#pragma unroll
        for (int e = 0; e < NEXP; ++e) if (e != i0 && p[e] > p[i1]) i1 = e;
        float w0 = p[i0], w1 = p[i1];
        float ws = w0 + w1;
        w0 /= ws; w1 /= ws;
        g_tok_eid[warp * 2 + 0] = i0;
        g_tok_eid[warp * 2 + 1] = i1;
        g_tok_w[warp * 2 + 0] = w0;
        g_tok_w[warp * 2 + 1] = w1;
        atomicAdd(&g_counts[i0], 1);
        atomicAdd(&g_counts[i1], 1);
    }
}

// ---------------- K2: plan ----------------
__global__ void plan_kernel() {
    if (threadIdx.x == 0) {
        int off = 0, tix = 0;
        for (int e = 0; e < NEXP; ++e) {
            g_cursor[e] = off;
            int tiles = (g_counts[e] + BM - 1) / BM;
            for (int i = 0; i < tiles; ++i) g_tile_e[tix++] = e;
            off += tiles * BM;
        }
        g_num_tiles = tix;
    }
}

// ---------------- K3: scatter ----------------
__global__ void scatter_kernel() {
    int t = blockIdx.x * blockDim.x + threadIdx.x;
    if (t >= T_TOK) return;
#pragma unroll
    for (int k = 0; k < TOPK; ++k) {
        int e = g_tok_eid[t * 2 + k];
        int r = atomicAdd(&g_cursor[e], 1);
        g_pair_tok[r] = t;
        g_pair_wt[r]  = g_tok_w[t * 2 + k];
        g_row_of[t * 2 + k] = r;
    }
}

// ---------------- K4/K5: fp16 tensor-core GEMM (m16n8k16 + ldmatrix) ----------------
// CTA 128x128, 4 warps of 64x64, BK=32, double-buffered static smem (~37.9 KB),
// 2 CTAs/SM. Operands converted to fp16 (RNE) at staging; fp32 accumulate.
// FFN1: scr1h = fp16(gelu(gather(x) @ w1 + b1))   (NDIM=F, KTOT=H)
// FFN2: scr2  = wt * (scr1h @ w2 + b2)            (NDIM=H, KTOT=F)
template <int NDIM, int KTOT, bool FFN1>
__global__ void __launch_bounds__(128, 2)
moe_gemm(const float* __restrict__ AinArg,
         const float* __restrict__ Wall,
         const float* __restrict__ biasAll) {
    const int mtile = blockIdx.y;
    if (mtile >= g_num_tiles) return;
    const int e  = g_tile_e[mtile];
    const int n0 = blockIdx.x * BN;

    const int tid  = threadIdx.x;
    const int lane = tid & 31;
    const int wid  = tid >> 5;     // 0..3
    const int wm   = wid >> 1;     // 0..1  (64-row slab)
    const int wn   = wid & 1;      // 0..1  (64-col slab)
    const int g    = lane >> 2;    // 0..7
    const int tig  = lane & 3;     // 0..3

    __shared__ __align__(16) __half As[2][BM][BK + A_PAD];   // 80 B rows
    __shared__ __align__(16) __half Bs[2][BK][BN + B_PAD];   // 272 B rows

    const float* W = Wall + (size_t)e * KTOT * NDIM;  // [K][N] row-major

    // ---- ldmatrix addresses (per-lane, fixed) ----
    const uint32_t sA = smem_to_u32(&As[0][0][0]);
    const uint32_t sB = smem_to_u32(&Bs[0][0][0]);
    uint32_t aAddr[4], bAddr[4];
#pragma unroll
    for (int mi = 0; mi < 4; ++mi) {
        int mbase = wm * 64 + mi * 16;
        aAddr[mi] = sA + (uint32_t)((mbase + (lane & 15)) * (BK + A_PAD) * 2
                                    + ((lane >> 4) & 1) * 16);
    }
#pragma unroll
    for (int nb = 0; nb < 4; ++nb) {
        int nbase = wn * 64 + nb * 16 + ((lane >> 4) & 1) * 8;
        bAddr[nb] = sB + (uint32_t)((lane & 15) * (BN + B_PAD) * 2 + nbase * 2);
    }

    // ---- staging indices: A 1024 8B-units -> 8/thread; B 1024 float4 -> 8/thread
    size_t a_off[8];
    int    a_row[8], a_q[8];
#pragma unroll
    for (int i = 0; i < 8; ++i) {
        int idx = i * 128 + tid;
        a_row[i] = idx >> 3;            // 0..127
        a_q[i]   = (idx & 7) * 4;       // halves/floats within row
        size_t srow;
        if (FFN1) {
            int t = g_pair_tok[mtile * BM + a_row[i]];
            if (t < 0) t = 0;
            srow = (size_t)t * KTOT;
        } else {
            srow = (size_t)(mtile * BM + a_row[i]) * KTOT;
        }
        a_off[i] = srow + a_q[i];
    }
    int b_k[8], b_n4[8];
#pragma unroll
    for (int i = 0; i < 8; ++i) {
        int idx = i * 128 + tid;
        b_k[i]  = idx >> 5;             // 0..31
        b_n4[i] = (idx & 31) * 4;       // 0..124
    }

    float c[4][8][4];
#pragma unroll
    for (int mi = 0; mi < 4; ++mi)
#pragma unroll
        for (int ni = 0; ni < 8; ++ni)
#pragma unroll
            for (int q = 0; q < 4; ++q) c[mi][ni][q] = 0.0f;

    uint2 ua[8], ub[8];

    // prologue: load chunk 0 into buffer 0
#pragma unroll
    for (int i = 0; i < 8; ++i) {
        if (FFN1)
            ua[i] = f4h4(*(const float4*)(AinArg + a_off[i]));
        else
            ua[i] = *(const uint2*)((const __half*)g_scr1h + a_off[i]);
    }
#pragma unroll
    for (int i = 0; i < 8; ++i)
        ub[i] = f4h4(*(const float4*)(W + (size_t)b_k[i] * NDIM + n0 + b_n4[i]));
#pragma unroll
    for (int i = 0; i < 8; ++i) *(uint2*)&As[0][a_row[i]][a_q[i]] = ua[i];
#pragma unroll
    for (int i = 0; i < 8; ++i) *(uint2*)&Bs[0][b_k[i]][b_n4[i]] = ub[i];
    __syncthreads();

    const int NK = KTOT / BK;
    int buf = 0;
    for (int kt = 0; kt < NK; ++kt) {
        if (kt + 1 < NK) {
            const int k0 = (kt + 1) * BK;
#pragma unroll
            for (int i = 0; i < 8; ++i) {
                if (FFN1)
                    ua[i] = f4h4(*(const float4*)(AinArg + a_off[i] + k0));
                else
                    ua[i] = *(const uint2*)((const __half*)g_scr1h + a_off[i] + k0);
            }
#pragma unroll
            for (int i = 0; i < 8; ++i)
                ub[i] = f4h4(*(const float4*)(W + (size_t)(k0 + b_k[i]) * NDIM + n0 + b_n4[i]));
        }
        const uint32_t aB = (uint32_t)buf * ABUF_BYTES;
        const uint32_t bB = (uint32_t)buf * BBUF_BYTES;
#pragma unroll
        for (int kk = 0; kk < 2; ++kk) {           // two k16 steps per chunk
            uint32_t af[4][4], bf[4][4];
#pragma unroll
            for (int mi = 0; mi < 4; ++mi)
                ldsm_x4(af[mi], aAddr[mi] + aB + kk * 32);
#pragma unroll
            for (int nb = 0; nb < 4; ++nb)
                ldsm_x4_t(bf[nb], bAddr[nb] + bB + kk * 16 * (BN + B_PAD) * 2);
#pragma unroll
            for (int mi = 0; mi < 4; ++mi)
#pragma unroll
                for (int ni = 0; ni < 8; ++ni)
                    mma_f16(c[mi][ni], af[mi], &bf[ni >> 1][(ni & 1) * 2]);
        }
        if (kt + 1 < NK) {
            int nb = buf ^ 1;
#pragma unroll
            for (int i = 0; i < 8; ++i) *(uint2*)&As[nb][a_row[i]][a_q[i]] = ua[i];
#pragma unroll
            for (int i = 0; i < 8; ++i) *(uint2*)&Bs[nb][b_k[i]][b_n4[i]] = ub[i];
            __syncthreads();
            buf = nb;
        }
    }

    // ---- epilogue (C layout of m16n8k16 == m16n8k8) ----
    const float* bias = biasAll + (size_t)e * NDIM + n0;
#pragma unroll
    for (int mi = 0; mi < 4; ++mi) {
        size_t r0 = (size_t)mtile * BM + wm * 64 + mi * 16 + g;
        float w0 = 1.0f, w1 = 1.0f;
        if (!FFN1) {
            w0 = g_pair_wt[r0];
            w1 = g_pair_wt[r0 + 8];
        }
#pragma unroll
        for (int ni = 0; ni < 8; ++ni) {
            int col = wn * 64 + ni * 8 + tig * 2;
            float b0 = bias[col], b1v = bias[col + 1];
            float v0 = c[mi][ni][0] + b0, v1 = c[mi][ni][1] + b1v;   // row g
            float v2 = c[mi][ni][2] + b0, v3 = c[mi][ni][3] + b1v;   // row g+8
            if (FFN1) {
                __half2 h0 = __floats2half2_rn(gelu_tanh(v0), gelu_tanh(v1));
                __half2 h1 = __floats2half2_rn(gelu_tanh(v2), gelu_tanh(v3));
                *(uint32_t*)&g_scr1h[r0 * NDIM + n0 + col]       = *(uint32_t*)&h0;
                *(uint32_t*)&g_scr1h[(r0 + 8) * NDIM + n0 + col] = *(uint32_t*)&h1;
            } else {
                float2 s0, s1;
                s0.x = v0 * w0; s0.y = v1 * w0;
                s1.x = v2 * w1; s1.y = v3 * w1;
                *(float2*)&g_scr2[r0 * NDIM + n0 + col] = s0;
                *(float2*)&g_scr2[(r0 + 8) * NDIM + n0 + col] = s1;
            }
        }
    }
}

// ---------------- K6: deterministic combine ----------------
__global__ void combine_kernel(float* __restrict__ out) {
    int idx = blockIdx.x * blockDim.x + threadIdx.x;   // over T_TOK * HDIM / 4
    int t  = idx / (HDIM / 4);
    int h4 = idx % (HDIM / 4);
    if (t >= T_TOK) return;
    size_t r0 = (size_t)g_row_of[t * 2 + 0];
    size_t r1 = (size_t)g_row_of[t * 2 + 1];
    float4 a = *(const float4*)&g_scr2[r0 * HDIM + h4 * 4];
    float4 b = *(const float4*)&g_scr2[r1 * HDIM + h4 * 4];
    float4 o;
    o.x = a.x + b.x; o.y = a.y + b.y; o.z = a.z + b.z; o.w = a.w + b.w;
    *(float4*)&out[(size_t)t * HDIM + h4 * 4] = o;
}

// ---------------- launch ----------------
extern "C" void kernel_launch(void* const* d_in, const int* in_sizes, int n_in,
                              void* d_out, int out_size) {
    const float* x  = (const float*)d_in[0];  // (B,S,H)
    const float* w1 = (const float*)d_in[1];  // (E,H,F)
    const float* b1 = (const float*)d_in[2];  // (E,F)
    const float* w2 = (const float*)d_in[3];  // (E,F,H)
    const float* b2 = (const float*)d_in[4];  // (E,H)
    const float* rw = (const float*)d_in[5];  // (H,E)
    const float* rb = (const float*)d_in[6];  // (E,)
    float* out = (float*)d_out;

    init_kernel<<<ROWCAP / 256, 256>>>();
    router_kernel<<<(T_TOK * 32) / 256, 256>>>(x, rw, rb);
    plan_kernel<<<1, 32>>>();
    scatter_kernel<<<T_TOK / 256, 256>>>();

    moe_gemm<FDIM, HDIM, true><<<dim3(FDIM / BN, MAXTILES), 128>>>(x, w1, b1);
    moe_gemm<HDIM, FDIM, false><<<dim3(HDIM / BN, MAXTILES), 128>>>(nullptr, w2, b2);

    combine_kernel<<<(T_TOK * HDIM / 4 + 255) / 256, 256>>>(out);
}

// round 14
// speedup vs baseline: 1.9007x; 1.2409x over previous
#include <cuda_runtime.h>
#include <cuda_fp16.h>
#include <cstdint>
#include <math.h>

// ---------------- problem constants ----------------
#define T_TOK 8192
#define HDIM  1024
#define FDIM  4096
#define NEXP  8
#define TOPK  2

// ---------------- GEMM tiling ----------------
#define BM 128
#define BN 128
#define BK 32
#define MAXTILES 136
#define ROWCAP   (MAXTILES * BM)

#define A_PAD 8     // halves; row = 40 halves = 80 B
#define B_PAD 8     // halves; row = 136 halves = 272 B
#define ABUF_BYTES (BM * (BK + A_PAD) * 2)   // 10240
#define BBUF_BYTES (BK * (BN + B_PAD) * 2)   // 8704

// ---------------- scratch (static device globals; no allocs) ----------------
// Referenced ONLY from device code (host-passed __device__ symbols decay to
// the host shadow address — the R4/R6 failure mode).
__device__ __half g_xh[(size_t)T_TOK * HDIM];        // fp16 x
__device__ __half g_w1h[(size_t)NEXP * HDIM * FDIM]; // fp16 w1
__device__ __half g_w2h[(size_t)NEXP * FDIM * HDIM]; // fp16 w2
__device__ __half g_scr1h[(size_t)ROWCAP * FDIM];    // fp16 gelu(x@w1+b1)
__device__ float  g_scr2[(size_t)ROWCAP * HDIM];
__device__ int    g_pair_tok[ROWCAP];
__device__ float  g_pair_wt[ROWCAP];
__device__ int    g_row_of[T_TOK * TOPK];
__device__ int    g_tok_eid[T_TOK * TOPK];
__device__ float  g_tok_w[T_TOK * TOPK];
__device__ int    g_counts[NEXP];
__device__ int    g_cursor[NEXP];
__device__ int    g_tile_e[MAXTILES];
__device__ int    g_num_tiles;

// ---------------- helpers ----------------
__device__ __forceinline__ uint32_t smem_to_u32(const void* p) {
    uint32_t a;
    asm("{ .reg .u64 t; cvta.to.shared.u64 t, %1; cvt.u32.u64 %0, t; }" : "=r"(a) : "l"(p));
    return a;
}

__device__ __forceinline__ float gelu_tanh(float v) {
    // jax.nn.gelu approximate=True
    float u = v * (0.7978845608028654f + 0.03567740813636141f * v * v);
    return 0.5f * v * (1.0f + tanhf(u));
}

__device__ __forceinline__ void ldsm_x4(uint32_t* r, uint32_t addr) {
    asm volatile("ldmatrix.sync.aligned.m8n8.x4.shared.b16 {%0,%1,%2,%3}, [%4];"
        : "=r"(r[0]), "=r"(r[1]), "=r"(r[2]), "=r"(r[3]) : "r"(addr));
}

__device__ __forceinline__ void ldsm_x4_t(uint32_t* r, uint32_t addr) {
    asm volatile("ldmatrix.sync.aligned.m8n8.x4.trans.shared.b16 {%0,%1,%2,%3}, [%4];"
        : "=r"(r[0]), "=r"(r[1]), "=r"(r[2]), "=r"(r[3]) : "r"(addr));
}

__device__ __forceinline__ void mma_f16(float* d, const uint32_t* a, const uint32_t* b) {
    asm volatile(
        "mma.sync.aligned.m16n8k16.row.col.f32.f16.f16.f32 "
        "{%0,%1,%2,%3},{%4,%5,%6,%7},{%8,%9},{%0,%1,%2,%3};\n"
        : "+f"(d[0]), "+f"(d[1]), "+f"(d[2]), "+f"(d[3])
        : "r"(a[0]), "r"(a[1]), "r"(a[2]), "r"(a[3]),
          "r"(b[0]), "r"(b[1]));
}

// ---------------- K0: reset per-call state ----------------
__global__ void init_kernel() {
    int i = blockIdx.x * blockDim.x + threadIdx.x;
    if (i < NEXP) g_counts[i] = 0;
    if (i < ROWCAP) {
        g_pair_tok[i] = -1;
        g_pair_wt[i]  = 0.0f;
    }
}

// ---------------- K1: router (one warp per token, fp64 accumulation) ----------------
__global__ void router_kernel(const float* __restrict__ x,
                              const float* __restrict__ rw,
                              const float* __restrict__ rb) {
    int warp = (blockIdx.x * blockDim.x + threadIdx.x) >> 5;
    if (warp >= T_TOK) return;
    int lane = threadIdx.x & 31;

    double acc[NEXP];
#pragma unroll
    for (int e = 0; e < NEXP; ++e) acc[e] = 0.0;

    const float* xr = x + (size_t)warp * HDIM;
    for (int h = lane; h < HDIM; h += 32) {
        double xv = (double)xr[h];
        const float* w = rw + h * NEXP;
#pragma unroll
        for (int e = 0; e < NEXP; ++e) acc[e] += xv * (double)w[e];
    }
#pragma unroll
    for (int off = 16; off; off >>= 1) {
#pragma unroll
        for (int e = 0; e < NEXP; ++e)
            acc[e] += __shfl_down_sync(0xffffffffu, acc[e], off);
    }
    if (lane == 0) {
        float lg[NEXP];
        float mx = -1e30f;
#pragma unroll
        for (int e = 0; e < NEXP; ++e) {
            lg[e] = (float)acc[e] + rb[e];
            mx = fmaxf(mx, lg[e]);
        }
        float p[NEXP];
        float s = 0.0f;
#pragma unroll
        for (int e = 0; e < NEXP; ++e) { p[e] = expf(lg[e] - mx); s += p[e]; }
        int i0 = 0;
#pragma unroll
        for (int e = 1; e < NEXP; ++e) if (p[e] > p[i0]) i0 = e;
        int i1 = (i0 == 0) ? 1 : 0;
#pragma unroll
        for (int e = 0; e < NEXP; ++e) if (e != i0 && p[e] > p[i1]) i1 = e;
        float w0 = p[i0], w1 = p[i1];
        float ws = w0 + w1;
        w0 /= ws; w1 /= ws;
        g_tok_eid[warp * 2 + 0] = i0;
        g_tok_eid[warp * 2 + 1] = i1;
        g_tok_w[warp * 2 + 0] = w0;
        g_tok_w[warp * 2 + 1] = w1;
        atomicAdd(&g_counts[i0], 1);
        atomicAdd(&g_counts[i1], 1);
    }
}

// ---------------- K2: plan ----------------
__global__ void plan_kernel() {
    if (threadIdx.x == 0) {
        int off = 0, tix = 0;
        for (int e = 0; e < NEXP; ++e) {
            g_cursor[e] = off;
            int tiles = (g_counts[e] + BM - 1) / BM;
            for (int i = 0; i < tiles; ++i) g_tile_e[tix++] = e;
            off += tiles * BM;
        }
        g_num_tiles = tix;
    }
}

// ---------------- K3: scatter ----------------
__global__ void scatter_kernel() {
    int t = blockIdx.x * blockDim.x + threadIdx.x;
    if (t >= T_TOK) return;
#pragma unroll
    for (int k = 0; k < TOPK; ++k) {
        int e = g_tok_eid[t * 2 + k];
        int r = atomicAdd(&g_cursor[e], 1);
        g_pair_tok[r] = t;
        g_pair_wt[r]  = g_tok_w[t * 2 + k];
        g_row_of[t * 2 + k] = r;
    }
}

// ---------------- K4: one-shot fp32 -> fp16 (RNE) conversion ----------------
// dst selected in DEVICE code: 0=g_xh, 1=g_w1h, 2=g_w2h. Thread = 8 elements.
template <int WHICH>
__global__ void to_half_kernel(const float* __restrict__ src, int n8) {
    int i = blockIdx.x * blockDim.x + threadIdx.x;
    if (i >= n8) return;
    __half* dst = (WHICH == 0) ? g_xh : (WHICH == 1) ? g_w1h : g_w2h;
    float4 a = ((const float4*)src)[i * 2];
    float4 b = ((const float4*)src)[i * 2 + 1];
    __half2 h0 = __floats2half2_rn(a.x, a.y);
    __half2 h1 = __floats2half2_rn(a.z, a.w);
    __half2 h2 = __floats2half2_rn(b.x, b.y);
    __half2 h3 = __floats2half2_rn(b.z, b.w);
    uint4 o;
    o.x = *(uint32_t*)&h0; o.y = *(uint32_t*)&h1;
    o.z = *(uint32_t*)&h2; o.w = *(uint32_t*)&h3;
    ((uint4*)dst)[i] = o;
}

// ---------------- K5/K6: fp16 tensor-core GEMM (m16n8k16 + ldmatrix) ----------------
// CTA 128x128, 4 warps of 64x64, BK=32, double-buffered static smem (~37 KB),
// 2 CTAs/SM. All operands pre-converted fp16 in global; fp32 accumulate.
// FFN1: scr1h = fp16(gelu(gather(g_xh) @ g_w1h + b1))   (NDIM=F, KTOT=H)
// FFN2: scr2  = wt * (g_scr1h @ g_w2h + b2)             (NDIM=H, KTOT=F)
template <int NDIM, int KTOT, bool FFN1>
__global__ void __launch_bounds__(128, 2)
moe_gemm(const float* __restrict__ biasAll) {
    const int mtile = blockIdx.y;
    if (mtile >= g_num_tiles) return;
    const int e  = g_tile_e[mtile];
    const int n0 = blockIdx.x * BN;

    const int tid  = threadIdx.x;
    const int lane = tid & 31;
    const int wid  = tid >> 5;     // 0..3
    const int wm   = wid >> 1;     // 0..1  (64-row slab)
    const int wn   = wid & 1;      // 0..1  (64-col slab)
    const int g    = lane >> 2;    // 0..7
    const int tig  = lane & 3;     // 0..3

    __shared__ __align__(16) __half As[2][BM][BK + A_PAD];   // 80 B rows
    __shared__ __align__(16) __half Bs[2][BK][BN + B_PAD];   // 272 B rows

    const __half* Ain = FFN1 ? (const __half*)g_xh  : (const __half*)g_scr1h;
    const __half* W   = (FFN1 ? (const __half*)g_w1h : (const __half*)g_w2h)
                        + (size_t)e * KTOT * NDIM;           // [K][N] row-major

    // ---- ldmatrix addresses (per-lane, fixed) ----
    const uint32_t sA = smem_to_u32(&As[0][0][0]);
    const uint32_t sB = smem_to_u32(&Bs[0][0][0]);
    uint32_t aAddr[4], bAddr[4];
#pragma unroll
    for (int mi = 0; mi < 4; ++mi) {
        int mbase = wm * 64 + mi * 16;
        aAddr[mi] = sA + (uint32_t)((mbase + (lane & 15)) * (BK + A_PAD) * 2
                                    + ((lane >> 4) & 1) * 16);
    }
#pragma unroll
    for (int nb = 0; nb < 4; ++nb) {
        int nbase = wn * 64 + nb * 16 + ((lane >> 4) & 1) * 8;
        bAddr[nb] = sB + (uint32_t)((lane & 15) * (BN + B_PAD) * 2 + nbase * 2);
    }

    // ---- staging: A 128x32 halves = 512 x16B units -> 4/thread;
    //               B  32x128 halves = 512 x16B units -> 4/thread
    size_t a_off[4];
    int    a_row[4], a_q[4];
#pragma unroll
    for (int i = 0; i < 4; ++i) {
        int idx = i * 128 + tid;
        a_row[i] = idx >> 2;            // 0..127
        a_q[i]   = (idx & 3) * 8;       // halves within row: 0,8,16,24
        size_t srow;
        if (FFN1) {
            int t = g_pair_tok[mtile * BM + a_row[i]];
            if (t < 0) t = 0;
            srow = (size_t)t * KTOT;
        } else {
            srow = (size_t)(mtile * BM + a_row[i]) * KTOT;
        }
        a_off[i] = srow + a_q[i];
    }
    int b_k[4], b_n8[4];
#pragma unroll
    for (int i = 0; i < 4; ++i) {
        int idx = i * 128 + tid;
        b_k[i]  = idx >> 4;             // 0..31
        b_n8[i] = (idx & 15) * 8;       // 0..120 halves
    }

    float c[4][8][4];
#pragma unroll
    for (int mi = 0; mi < 4; ++mi)
#pragma unroll
        for (int ni = 0; ni < 8; ++ni)
#pragma unroll
            for (int q = 0; q < 4; ++q) c[mi][ni][q] = 0.0f;

    uint4 ua[4], ub[4];

    // prologue: load chunk 0 into buffer 0
#pragma unroll
    for (int i = 0; i < 4; ++i) ua[i] = *(const uint4*)(Ain + a_off[i]);
#pragma unroll
    for (int i = 0; i < 4; ++i)
        ub[i] = *(const uint4*)(W + (size_t)b_k[i] * NDIM + n0 + b_n8[i]);
#pragma unroll
    for (int i = 0; i < 4; ++i) *(uint4*)&As[0][a_row[i]][a_q[i]] = ua[i];
#pragma unroll
    for (int i = 0; i < 4; ++i) *(uint4*)&Bs[0][b_k[i]][b_n8[i]] = ub[i];
    __syncthreads();

    const int NK = KTOT / BK;
    int buf = 0;
    for (int kt = 0; kt < NK; ++kt) {
        if (kt + 1 < NK) {
            const int k0 = (kt + 1) * BK;
#pragma unroll
            for (int i = 0; i < 4; ++i)
                ua[i] = *(const uint4*)(Ain + a_off[i] + k0);
#pragma unroll
            for (int i = 0; i < 4; ++i)
                ub[i] = *(const uint4*)(W + (size_t)(k0 + b_k[i]) * NDIM + n0 + b_n8[i]);
        }
        const uint32_t aB = (uint32_t)buf * ABUF_BYTES;
        const uint32_t bB = (uint32_t)buf * BBUF_BYTES;
#pragma unroll
        for (int kk = 0; kk < 2; ++kk) {           // two k16 steps per chunk
            uint32_t af[4][4], bf[4][4];
#pragma unroll
            for (int mi = 0; mi < 4; ++mi)
                ldsm_x4(af[mi], aAddr[mi] + aB + kk * 32);
#pragma unroll
            for (int nb = 0; nb < 4; ++nb)
                ldsm_x4_t(bf[nb], bAddr[nb] + bB + kk * 16 * (BN + B_PAD) * 2);
#pragma unroll
            for (int mi = 0; mi < 4; ++mi)
#pragma unroll
                for (int ni = 0; ni < 8; ++ni)
                    mma_f16(c[mi][ni], af[mi], &bf[ni >> 1][(ni & 1) * 2]);
        }
        if (kt + 1 < NK) {
            int nb = buf ^ 1;
#pragma unroll
            for (int i = 0; i < 4; ++i) *(uint4*)&As[nb][a_row[i]][a_q[i]] = ua[i];
#pragma unroll
            for (int i = 0; i < 4; ++i) *(uint4*)&Bs[nb][b_k[i]][b_n8[i]] = ub[i];
            __syncthreads();
            buf = nb;
        }
    }

    // ---- epilogue (C layout of m16n8k16 == m16n8k8) ----
    const float* bias = biasAll + (size_t)e * NDIM + n0;
#pragma unroll
    for (int mi = 0; mi < 4; ++mi) {
        size_t r0 = (size_t)mtile * BM + wm * 64 + mi * 16 + g;
        float w0 = 1.0f, w1 = 1.0f;
        if (!FFN1) {
            w0 = g_pair_wt[r0];
            w1 = g_pair_wt[r0 + 8];
        }
#pragma unroll
        for (int ni = 0; ni < 8; ++ni) {
            int col = wn * 64 + ni * 8 + tig * 2;
            float b0 = bias[col], b1v = bias[col + 1];
            float v0 = c[mi][ni][0] + b0, v1 = c[mi][ni][1] + b1v;   // row g
            float v2 = c[mi][ni][2] + b0, v3 = c[mi][ni][3] + b1v;   // row g+8
            if (FFN1) {
                __half2 h0 = __floats2half2_rn(gelu_tanh(v0), gelu_tanh(v1));
                __half2 h1 = __floats2half2_rn(gelu_tanh(v2), gelu_tanh(v3));
                *(uint32_t*)&g_scr1h[r0 * NDIM + n0 + col]       = *(uint32_t*)&h0;
                *(uint32_t*)&g_scr1h[(r0 + 8) * NDIM + n0 + col] = *(uint32_t*)&h1;
            } else {
                float2 s0, s1;
                s0.x = v0 * w0; s0.y = v1 * w0;
                s1.x = v2 * w1; s1.y = v3 * w1;
                *(float2*)&g_scr2[r0 * NDIM + n0 + col] = s0;
                *(float2*)&g_scr2[(r0 + 8) * NDIM + n0 + col] = s1;
            }
        }
    }
}

// ---------------- K7: deterministic combine ----------------
__global__ void combine_kernel(float* __restrict__ out) {
    int idx = blockIdx.x * blockDim.x + threadIdx.x;   // over T_TOK * HDIM / 4
    int t  = idx / (HDIM / 4);
    int h4 = idx % (HDIM / 4);
    if (t >= T_TOK) return;
    size_t r0 = (size_t)g_row_of[t * 2 + 0];
    size_t r1 = (size_t)g_row_of[t * 2 + 1];
    float4 a = *(const float4*)&g_scr2[r0 * HDIM + h4 * 4];
    float4 b = *(const float4*)&g_scr2[r1 * HDIM + h4 * 4];
    float4 o;
    o.x = a.x + b.x; o.y = a.y + b.y; o.z = a.z + b.z; o.w = a.w + b.w;
    *(float4*)&out[(size_t)t * HDIM + h4 * 4] = o;
}

// ---------------- launch ----------------
extern "C" void kernel_launch(void* const* d_in, const int* in_sizes, int n_in,
                              void* d_out, int out_size) {
    const float* x  = (const float*)d_in[0];  // (B,S,H)
    const float* w1 = (const float*)d_in[1];  // (E,H,F)
    const float* b1 = (const float*)d_in[2];  // (E,F)
    const float* w2 = (const float*)d_in[3];  // (E,F,H)
    const float* b2 = (const float*)d_in[4];  // (E,H)
    const float* rw = (const float*)d_in[5];  // (H,E)
    const float* rb = (const float*)d_in[6];  // (E,)
    float* out = (float*)d_out;

    init_kernel<<<ROWCAP / 256, 256>>>();
    router_kernel<<<(T_TOK * 32) / 256, 256>>>(x, rw, rb);
    plan_kernel<<<1, 32>>>();
    scatter_kernel<<<T_TOK / 256, 256>>>();

    // one-shot fp32 -> fp16 operand conversion
    {
        int n8x = T_TOK * HDIM / 8;
        int n8w = NEXP * HDIM * FDIM / 8;
        to_half_kernel<0><<<(n8x + 255) / 256, 256>>>(x, n8x);
        to_half_kernel<1><<<(n8w + 255) / 256, 256>>>(w1, n8w);
        to_half_kernel<2><<<(n8w + 255) / 256, 256>>>(w2, n8w);
    }

    moe_gemm<FDIM, HDIM, true><<<dim3(FDIM / BN, MAXTILES), 128>>>(b1);
    moe_gemm<HDIM, FDIM, false><<<dim3(HDIM / BN, MAXTILES), 128>>>(b2);

    combine_kernel<<<(T_TOK * HDIM / 4 + 255) / 256, 256>>>(out);
}

// round 16
// speedup vs baseline: 1.9102x; 1.0050x over previous
#include <cuda_runtime.h>
#include <cuda_fp16.h>
#include <cstdint>
#include <math.h>

// ---------------- problem constants ----------------
#define T_TOK 8192
#define HDIM  1024
#define FDIM  4096
#define NEXP  8
#define TOPK  2

// ---------------- GEMM tiling ----------------
#define BM 128
#define BN 128
#define BK 32
#define MAXTILES 136
#define ROWCAP   (MAXTILES * BM)

#define A_PAD 8     // halves; row = 40 halves = 80 B
#define B_PAD 8     // halves; row = 136 halves = 272 B
#define ABUF_BYTES (BM * (BK + A_PAD) * 2)   // 10240
#define BBUF_BYTES (BK * (BN + B_PAD) * 2)   // 8704

// ---------------- scratch (static device globals; no allocs) ----------------
// Referenced ONLY from device code (host-passed __device__ symbols decay to
// the host shadow address — the R4/R6 failure mode).
__device__ __half g_xh[(size_t)T_TOK * HDIM];        // fp16 x (written by router)
__device__ __half g_w1h[(size_t)NEXP * HDIM * FDIM]; // fp16 w1
__device__ __half g_w2h[(size_t)NEXP * FDIM * HDIM]; // fp16 w2
__device__ __half g_scr1h[(size_t)ROWCAP * FDIM];    // fp16 gelu(x@w1+b1)
__device__ __half g_scr2h[(size_t)ROWCAP * HDIM];    // fp16 wt*(h@w2+b2)
__device__ int    g_pair_tok[ROWCAP];
__device__ float  g_pair_wt[ROWCAP];
__device__ int    g_row_of[T_TOK * TOPK];
__device__ int    g_tok_eid[T_TOK * TOPK];
__device__ float  g_tok_w[T_TOK * TOPK];
__device__ int    g_counts[NEXP];
__device__ int    g_cursor[NEXP];
__device__ int    g_tile_e[MAXTILES];
__device__ int    g_num_tiles;

// ---------------- helpers ----------------
__device__ __forceinline__ uint32_t smem_to_u32(const void* p) {
    uint32_t a;
    asm("{ .reg .u64 t; cvta.to.shared.u64 t, %1; cvt.u32.u64 %0, t; }" : "=r"(a) : "l"(p));
    return a;
}

__device__ __forceinline__ float gelu_tanh(float v) {
    // jax.nn.gelu approximate=True
    float u = v * (0.7978845608028654f + 0.03567740813636141f * v * v);
    return 0.5f * v * (1.0f + tanhf(u));
}

__device__ __forceinline__ void ldsm_x4(uint32_t* r, uint32_t addr) {
    asm volatile("ldmatrix.sync.aligned.m8n8.x4.shared.b16 {%0,%1,%2,%3}, [%4];"
        : "=r"(r[0]), "=r"(r[1]), "=r"(r[2]), "=r"(r[3]) : "r"(addr));
}

__device__ __forceinline__ void ldsm_x4_t(uint32_t* r, uint32_t addr) {
    asm volatile("ldmatrix.sync.aligned.m8n8.x4.trans.shared.b16 {%0,%1,%2,%3}, [%4];"
        : "=r"(r[0]), "=r"(r[1]), "=r"(r[2]), "=r"(r[3]) : "r"(addr));
}

__device__ __forceinline__ void mma_f16(float* d, const uint32_t* a, const uint32_t* b) {
    asm volatile(
        "mma.sync.aligned.m16n8k16.row.col.f32.f16.f16.f32 "
        "{%0,%1,%2,%3},{%4,%5,%6,%7},{%8,%9},{%0,%1,%2,%3};\n"
        : "+f"(d[0]), "+f"(d[1]), "+f"(d[2]), "+f"(d[3])
        : "r"(a[0]), "r"(a[1]), "r"(a[2]), "r"(a[3]),
          "r"(b[0]), "r"(b[1]));
}

// ---------------- K0: reset per-call state ----------------
__global__ void init_kernel() {
    int i = blockIdx.x * blockDim.x + threadIdx.x;
    if (i < NEXP) g_counts[i] = 0;
    if (i < ROWCAP) {
        g_pair_tok[i] = -1;
        g_pair_wt[i]  = 0.0f;
    }
}

// ---------------- K1: router (one warp per token, fp64 accumulation) ----------------
// Also converts this token's row of x to fp16 into g_xh (fused — x is already
// being streamed here).
__global__ void router_kernel(const float* __restrict__ x,
                              const float* __restrict__ rw,
                              const float* __restrict__ rb) {
    int warp = (blockIdx.x * blockDim.x + threadIdx.x) >> 5;
    if (warp >= T_TOK) return;
    int lane = threadIdx.x & 31;

    double acc[NEXP];
#pragma unroll
    for (int e = 0; e < NEXP; ++e) acc[e] = 0.0;

    const float* xr = x + (size_t)warp * HDIM;
    __half* xh = g_xh + (size_t)warp * HDIM;
    for (int h = lane; h < HDIM; h += 32) {
        float xv = xr[h];
        xh[h] = __float2half_rn(xv);
        double xd = (double)xv;
        const float* w = rw + h * NEXP;
#pragma unroll
        for (int e = 0; e < NEXP; ++e) acc[e] += xd * (double)w[e];
    }
#pragma unroll
    for (int off = 16; off; off >>= 1) {
#pragma unroll
        for (int e = 0; e < NEXP; ++e)
            acc[e] += __shfl_down_sync(0xffffffffu, acc[e], off);
    }
    if (lane == 0) {
        float lg[NEXP];
        float mx = -1e30f;
#pragma unroll
        for (int e = 0; e < NEXP; ++e) {
            lg[e] = (float)acc[e] + rb[e];
            mx = fmaxf(mx, lg[e]);
        }
        float p[NEXP];
        float s = 0.0f;
#pragma unroll
        for (int e = 0; e < NEXP; ++e) { p[e] = expf(lg[e] - mx); s += p[e]; }
        int i0 = 0;
#pragma unroll
        for (int e = 1; e < NEXP; ++e) if (p[e] > p[i0]) i0 = e;
        int i1 = (i0 == 0) ? 1 : 0;
#pragma unroll
        for (int e = 0; e < NEXP; ++e) if (e != i0 && p[e] > p[i1]) i1 = e;
        float w0 = p[i0], w1 = p[i1];
        float ws = w0 + w1;
        w0 /= ws; w1 /= ws;
        g_tok_eid[warp * 2 + 0] = i0;
        g_tok_eid[warp * 2 + 1] = i1;
        g_tok_w[warp * 2 + 0] = w0;
        g_tok_w[warp * 2 + 1] = w1;
        atomicAdd(&g_counts[i0], 1);
        atomicAdd(&g_counts[i1], 1);
    }
}

// ---------------- K2: plan ----------------
__global__ void plan_kernel() {
    if (threadIdx.x == 0) {
        int off = 0, tix = 0;
        for (int e = 0; e < NEXP; ++e) {
            g_cursor[e] = off;
            int tiles = (g_counts[e] + BM - 1) / BM;
            for (int i = 0; i < tiles; ++i) g_tile_e[tix++] = e;
            off += tiles * BM;
        }
        g_num_tiles = tix;
    }
}

// ---------------- K3: scatter ----------------
__global__ void scatter_kernel() {
    int t = blockIdx.x * blockDim.x + threadIdx.x;
    if (t >= T_TOK) return;
#pragma unroll
    for (int k = 0; k < TOPK; ++k) {
        int e = g_tok_eid[t * 2 + k];
        int r = atomicAdd(&g_cursor[e], 1);
        g_pair_tok[r] = t;
        g_pair_wt[r]  = g_tok_w[t * 2 + k];
        g_row_of[t * 2 + k] = r;
    }
}

// ---------------- K4: one-shot fp32 -> fp16 (RNE) weight conversion ----------------
// dst selected in DEVICE code: 1=g_w1h, 2=g_w2h. Thread = 8 elements.
template <int WHICH>
__global__ void to_half_kernel(const float* __restrict__ src, int n8) {
    int i = blockIdx.x * blockDim.x + threadIdx.x;
    if (i >= n8) return;
    __half* dst = (WHICH == 1) ? g_w1h : g_w2h;
    float4 a = ((const float4*)src)[i * 2];
    float4 b = ((const float4*)src)[i * 2 + 1];
    __half2 h0 = __floats2half2_rn(a.x, a.y);
    __half2 h1 = __floats2half2_rn(a.z, a.w);
    __half2 h2 = __floats2half2_rn(b.x, b.y);
    __half2 h3 = __floats2half2_rn(b.z, b.w);
    uint4 o;
    o.x = *(uint32_t*)&h0; o.y = *(uint32_t*)&h1;
    o.z = *(uint32_t*)&h2; o.w = *(uint32_t*)&h3;
    ((uint4*)dst)[i] = o;
}

// ---------------- K5/K6: fp16 tensor-core GEMM (m16n8k16 + ldmatrix) ----------------
// CTA 128x128, 4 warps of 64x64, BK=32, double-buffered static smem (~37 KB),
// 2 CTAs/SM. All operands fp16 in global; fp32 accumulate.
// FFN1: scr1h = fp16(gelu(gather(g_xh) @ g_w1h + b1))   (NDIM=F, KTOT=H)
// FFN2: scr2h = fp16(wt * (g_scr1h @ g_w2h + b2))       (NDIM=H, KTOT=F)
template <int NDIM, int KTOT, bool FFN1>
__global__ void __launch_bounds__(128, 2)
moe_gemm(const float* __restrict__ biasAll) {
    const int mtile = blockIdx.y;
    if (mtile >= g_num_tiles) return;
    const int e  = g_tile_e[mtile];
    const int n0 = blockIdx.x * BN;

    const int tid  = threadIdx.x;
    const int lane = tid & 31;
    const int wid  = tid >> 5;     // 0..3
    const int wm   = wid >> 1;     // 0..1  (64-row slab)
    const int wn   = wid & 1;      // 0..1  (64-col slab)
    const int g    = lane >> 2;    // 0..7
    const int tig  = lane & 3;     // 0..3

    __shared__ __align__(16) __half As[2][BM][BK + A_PAD];   // 80 B rows
    __shared__ __align__(16) __half Bs[2][BK][BN + B_PAD];   // 272 B rows

    const __half* Ain = FFN1 ? (const __half*)g_xh  : (const __half*)g_scr1h;
    const __half* W   = (FFN1 ? (const __half*)g_w1h : (const __half*)g_w2h)
                        + (size_t)e * KTOT * NDIM;           // [K][N] row-major

    // ---- ldmatrix addresses (per-lane, fixed) ----
    const uint32_t sA = smem_to_u32(&As[0][0][0]);
    const uint32_t sB = smem_to_u32(&Bs[0][0][0]);
    uint32_t aAddr[4], bAddr[4];
#pragma unroll
    for (int mi = 0; mi < 4; ++mi) {
        int mbase = wm * 64 + mi * 16;
        aAddr[mi] = sA + (uint32_t)((mbase + (lane & 15)) * (BK + A_PAD) * 2
                                    + ((lane >> 4) & 1) * 16);
    }
#pragma unroll
    for (int nb = 0; nb < 4; ++nb) {
        int nbase = wn * 64 + nb * 16 + ((lane >> 4) & 1) * 8;
        bAddr[nb] = sB + (uint32_t)((lane & 15) * (BN + B_PAD) * 2 + nbase * 2);
    }

    // ---- staging: A 128x32 halves = 512 x16B units -> 4/thread;
    //               B  32x128 halves = 512 x16B units -> 4/thread
    size_t a_off[4];
    int    a_row[4], a_q[4];
#pragma unroll
    for (int i = 0; i < 4; ++i) {
        int idx = i * 128 + tid;
        a_row[i] = idx >> 2;            // 0..127
        a_q[i]   = (idx & 3) * 8;       // halves within row: 0,8,16,24
        size_t srow;
        if (FFN1) {
            int t = g_pair_tok[mtile * BM + a_row[i]];
            if (t < 0) t = 0;
            srow = (size_t)t * KTOT;
        } else {
            srow = (size_t)(mtile * BM + a_row[i]) * KTOT;
        }
        a_off[i] = srow + a_q[i];
    }
    int b_k[4], b_n8[4];
#pragma unroll
    for (int i = 0; i < 4; ++i) {
        int idx = i * 128 + tid;
        b_k[i]  = idx >> 4;             // 0..31
        b_n8[i] = (idx & 15) * 8;       // 0..120 halves
    }

    float c[4][8][4];
#pragma unroll
    for (int mi = 0; mi < 4; ++mi)
#pragma unroll
        for (int ni = 0; ni < 8; ++ni)
#pragma unroll
            for (int q = 0; q < 4; ++q) c[mi][ni][q] = 0.0f;

    uint4 ua[4], ub[4];

    // prologue: load chunk 0 into buffer 0
#pragma unroll
    for (int i = 0; i < 4; ++i) ua[i] = *(const uint4*)(Ain + a_off[i]);
#pragma unroll
    for (int i = 0; i < 4; ++i)
        ub[i] = *(const uint4*)(W + (size_t)b_k[i] * NDIM + n0 + b_n8[i]);
#pragma unroll
    for (int i = 0; i < 4; ++i) *(uint4*)&As[0][a_row[i]][a_q[i]] = ua[i];
#pragma unroll
    for (int i = 0; i < 4; ++i) *(uint4*)&Bs[0][b_k[i]][b_n8[i]] = ub[i];
    __syncthreads();

    const int NK = KTOT / BK;
    int buf = 0;
    for (int kt = 0; kt < NK; ++kt) {
        if (kt + 1 < NK) {
            const int k0 = (kt + 1) * BK;
#pragma unroll
            for (int i = 0; i < 4; ++i)
                ua[i] = *(const uint4*)(Ain + a_off[i] + k0);
#pragma unroll
            for (int i = 0; i < 4; ++i)
                ub[i] = *(const uint4*)(W + (size_t)(k0 + b_k[i]) * NDIM + n0 + b_n8[i]);
        }
        const uint32_t aB = (uint32_t)buf * ABUF_BYTES;
        const uint32_t bB = (uint32_t)buf * BBUF_BYTES;
#pragma unroll
        for (int kk = 0; kk < 2; ++kk) {           // two k16 steps per chunk
            uint32_t af[4][4], bf[4][4];
#pragma unroll
            for (int mi = 0; mi < 4; ++mi)
                ldsm_x4(af[mi], aAddr[mi] + aB + kk * 32);
#pragma unroll
            for (int nb = 0; nb < 4; ++nb)
                ldsm_x4_t(bf[nb], bAddr[nb] + bB + kk * 16 * (BN + B_PAD) * 2);
#pragma unroll
            for (int mi = 0; mi < 4; ++mi)
#pragma unroll
                for (int ni = 0; ni < 8; ++ni)
                    mma_f16(c[mi][ni], af[mi], &bf[ni >> 1][(ni & 1) * 2]);
        }
        if (kt + 1 < NK) {
            int nb = buf ^ 1;
#pragma unroll
            for (int i = 0; i < 4; ++i) *(uint4*)&As[nb][a_row[i]][a_q[i]] = ua[i];
#pragma unroll
            for (int i = 0; i < 4; ++i) *(uint4*)&Bs[nb][b_k[i]][b_n8[i]] = ub[i];
            __syncthreads();
            buf = nb;
        }
    }

    // ---- epilogue (C layout of m16n8k16 == m16n8k8); fp16 stores both phases ----
    const float* bias = biasAll + (size_t)e * NDIM + n0;
    __half* Cout = FFN1 ? (__half*)g_scr1h : (__half*)g_scr2h;
#pragma unroll
    for (int mi = 0; mi < 4; ++mi) {
        size_t r0 = (size_t)mtile * BM + wm * 64 + mi * 16 + g;
        float w0 = 1.0f, w1 = 1.0f;
        if (!FFN1) {
            w0 = g_pair_wt[r0];
            w1 = g_pair_wt[r0 + 8];
        }
#pragma unroll
        for (int ni = 0; ni < 8; ++ni) {
            int col = wn * 64 + ni * 8 + tig * 2;
            float b0 = bias[col], b1v = bias[col + 1];
            float v0 = c[mi][ni][0] + b0, v1 = c[mi][ni][1] + b1v;   // row g
            float v2 = c[mi][ni][2] + b0, v3 = c[mi][ni][3] + b1v;   // row g+8
            __half2 h0, h1;
            if (FFN1) {
                h0 = __floats2half2_rn(gelu_tanh(v0), gelu_tanh(v1));
                h1 = __floats2half2_rn(gelu_tanh(v2), gelu_tanh(v3));
            } else {
                h0 = __floats2half2_rn(v0 * w0, v1 * w0);
                h1 = __floats2half2_rn(v2 * w1, v3 * w1);
            }
            *(uint32_t*)&Cout[r0 * NDIM + n0 + col]       = *(uint32_t*)&h0;
            *(uint32_t*)&Cout[(r0 + 8) * NDIM + n0 + col] = *(uint32_t*)&h1;
        }
    }
}

// ---------------- K7: deterministic combine (fp16 in, fp32 sum + out) ----------------
__global__ void combine_kernel(float* __restrict__ out) {
    int idx = blockIdx.x * blockDim.x + threadIdx.x;   // over T_TOK * HDIM / 8
    int t  = idx / (HDIM / 8);
    int h8 = idx % (HDIM / 8);
    if (t >= T_TOK) return;
    size_t r0 = (size_t)g_row_of[t * 2 + 0];
    size_t r1 = (size_t)g_row_of[t * 2 + 1];
    uint4 pa = *(const uint4*)&g_scr2h[r0 * HDIM + h8 * 8];
    uint4 pb = *(const uint4*)&g_scr2h[r1 * HDIM + h8 * 8];
    const uint32_t* wa = &pa.x;
    const uint32_t* wb = &pb.x;
    float o[8];                         // contiguous — fixes the R15 UB
#pragma unroll
    for (int j = 0; j < 4; ++j) {
        float2 fa = __half22float2(*(const __half2*)&wa[j]);
        float2 fb = __half22float2(*(const __half2*)&wb[j]);
        o[j * 2 + 0] = fa.x + fb.x;
        o[j * 2 + 1] = fa.y + fb.y;
    }
    float* dst = out + (size_t)t * HDIM + h8 * 8;
    *(float4*)(dst)     = make_float4(o[0], o[1], o[2], o[3]);
    *(float4*)(dst + 4) = make_float4(o[4], o[5], o[6], o[7]);
}

// ---------------- launch ----------------
extern "C" void kernel_launch(void* const* d_in, const int* in_sizes, int n_in,
                              void* d_out, int out_size) {
    const float* x  = (const float*)d_in[0];  // (B,S,H)
    const float* w1 = (const float*)d_in[1];  // (E,H,F)
    const float* b1 = (const float*)d_in[2];  // (E,F)
    const float* w2 = (const float*)d_in[3];  // (E,F,H)
    const float* b2 = (const float*)d_in[4];  // (E,H)
    const float* rw = (const float*)d_in[5];  // (H,E)
    const float* rb = (const float*)d_in[6];  // (E,)
    float* out = (float*)d_out;

    init_kernel<<<ROWCAP / 256, 256>>>();
    router_kernel<<<(T_TOK * 32) / 256, 256>>>(x, rw, rb);   // also writes g_xh
    plan_kernel<<<1, 32>>>();
    scatter_kernel<<<T_TOK / 256, 256>>>();

    // one-shot fp32 -> fp16 weight conversion
    {
        int n8w = NEXP * HDIM * FDIM / 8;
        to_half_kernel<1><<<(n8w + 255) / 256, 256>>>(w1, n8w);
        to_half_kernel<2><<<(n8w + 255) / 256, 256>>>(w2, n8w);
    }

    moe_gemm<FDIM, HDIM, true><<<dim3(FDIM / BN, MAXTILES), 128>>>(b1);
    moe_gemm<HDIM, FDIM, false><<<dim3(HDIM / BN, MAXTILES), 128>>>(b2);

    combine_kernel<<<(T_TOK * HDIM / 8 + 255) / 256, 256>>>(out);
}